// round 11
// baseline (speedup 1.0000x reference)
#include <cuda_runtime.h>
#include <cuda_bf16.h>
#include <math.h>
#include <stdint.h>

using bf16 = __nv_bfloat16;

// ---------------- problem constants ----------------
#define EMBED   1024
#define NHEADS  16
#define HDIM    64
#define SCALE   0.125f
#define NQ      100
#define NPATCH  1024
#define SEQ     1124
#define SEQP    1152
#define BATCH   8
#define MTOT    (BATCH*SEQ)      // 8992
#define MLPH    4096
#define LN_EPS  1e-6f
#define NEG_BIG (-1.0e9f)

// smem bytes for a 2-stage pipeline of (Ah,Al,Bh,Bl) tiles, BKP=40
constexpr int smem_bytes(int BM, int BN) {
    return 2 /*stages*/ * (2*BM*40 + 2*BN*40) /*elems*/ * 2 /*sizeof bf16*/;
}

// flash attention tile params
#define SN    64
#define NCH   (SEQP/SN)
#define KVP   72
constexpr int FLASH_SMEM = (2*128*KVP + 2*4*64*KVP) * 2;

// ---------------- scratch ----------------
__device__ bf16  g_xn_h [MTOT*EMBED],  g_xn_l [MTOT*EMBED];
__device__ bf16  g_qk_h [(long)MTOT*2048], g_qk_l [(long)MTOT*2048];
__device__ bf16  g_vT_h [(long)BATCH*NHEADS*HDIM*SEQP], g_vT_l [(long)BATCH*NHEADS*HDIM*SEQP];
__device__ bf16  g_ao_h [MTOT*EMBED],  g_ao_l [MTOT*EMBED];
__device__ bf16  g_h1_h [(long)MTOT*MLPH], g_h1_l [(long)MTOT*MLPH];
__device__ float g_xmid [(long)MTOT*EMBED];
__device__ bf16  g_wqkv_h[(long)3072*1024], g_wqkv_l[(long)3072*1024];
__device__ bf16  g_wprj_h[(long)1024*1024], g_wprj_l[(long)1024*1024];
__device__ bf16  g_wfc1_h[(long)4096*1024], g_wfc1_l[(long)4096*1024];
__device__ bf16  g_wfc2_h[(long)1024*4096], g_wfc2_l[(long)1024*4096];

// ---------------- helpers ----------------
__device__ __forceinline__ void bf16_split(float v, bf16& h, bf16& l){
    h = __float2bfloat16(v);
    l = __float2bfloat16(v - __bfloat162float(h));
}
__device__ __forceinline__ float warpSum(float v){
    #pragma unroll
    for (int o = 16; o > 0; o >>= 1) v += __shfl_xor_sync(0xffffffffu, v, o);
    return v;
}
__device__ __forceinline__ void cp16(uint32_t s, const void* g, bool valid){
    asm volatile("cp.async.cg.shared.global [%0], [%1], 16, %2;"
                 :: "r"(s), "l"(g), "r"(valid ? 16 : 0));
}
#define CP_COMMIT() asm volatile("cp.async.commit_group;" ::: "memory")
#define CP_WAIT0()  asm volatile("cp.async.wait_group 0;" ::: "memory")
#define CP_WAIT1()  asm volatile("cp.async.wait_group 1;" ::: "memory")
__device__ __forceinline__ uint32_t smaddr(const void* p){
    return (uint32_t)__cvta_generic_to_shared(p);
}
__device__ __forceinline__ uint32_t pack_bf16x2(bf16 a, bf16 b){
    __nv_bfloat162 t(a, b);
    return *reinterpret_cast<uint32_t*>(&t);
}

#define MMA_BF16(c, a, b) \
    asm volatile("mma.sync.aligned.m16n8k16.row.col.f32.bf16.bf16.f32 " \
                 "{%0,%1,%2,%3},{%4,%5,%6,%7},{%8,%9},{%0,%1,%2,%3};" \
                 : "+f"(c[0]), "+f"(c[1]), "+f"(c[2]), "+f"(c[3]) \
                 : "r"(a[0]), "r"(a[1]), "r"(a[2]), "r"(a[3]), "r"(b[0]), "r"(b[1]))

#define LDSM4(r0, r1, r2, r3, addr) \
    asm volatile("ldmatrix.sync.aligned.m8n8.x4.shared.b16 {%0,%1,%2,%3}, [%4];" \
                 : "=r"(r0), "=r"(r1), "=r"(r2), "=r"(r3) : "r"(addr))

// ---------------- weight transpose + split ----------------
__global__ void wsplitT(const float* __restrict__ w, bf16* __restrict__ oh,
                        bf16* __restrict__ ol, int K, int N)
{
    __shared__ float sm[32][33];
    const int n0 = blockIdx.x*32, k0 = blockIdx.y*32;
    #pragma unroll
    for (int i = 0; i < 4; i++) {
        const int k = threadIdx.y + i*8;
        sm[k][threadIdx.x] = w[(long)(k0+k)*N + n0 + threadIdx.x];
    }
    __syncthreads();
    #pragma unroll
    for (int i = 0; i < 4; i++) {
        const int nl = threadIdx.y + i*8;
        const float v = sm[threadIdx.x][nl];
        bf16 h, l; bf16_split(v, h, l);
        const long o = (long)(n0+nl)*K + k0 + threadIdx.x;
        oh[o] = h; ol[o] = l;
    }
}

// ---------------- LayerNorm -> hi/lo bf16 ----------------
__global__ void ln_kernel(const float* __restrict__ x,
                          const float* __restrict__ gamma,
                          const float* __restrict__ beta,
                          bf16* __restrict__ oh, bf16* __restrict__ ol)
{
    const int row = blockIdx.x;
    const int tid = threadIdx.x;
    const float4 v = reinterpret_cast<const float4*>(x + (size_t)row*EMBED)[tid];
    float s  = v.x + v.y + v.z + v.w;
    float ss = v.x*v.x + v.y*v.y + v.z*v.z + v.w*v.w;
    s = warpSum(s); ss = warpSum(ss);
    __shared__ float sh1[8], sh2[8];
    const int w = tid >> 5, l = tid & 31;
    if (l == 0) { sh1[w] = s; sh2[w] = ss; }
    __syncthreads();
    if (w == 0) {
        float a = (l < 8) ? sh1[l] : 0.f;
        float b = (l < 8) ? sh2[l] : 0.f;
        a = warpSum(a); b = warpSum(b);
        if (l == 0) { sh1[0] = a; sh2[0] = b; }
    }
    __syncthreads();
    const float mean = sh1[0] * (1.0f/EMBED);
    const float var  = sh2[0] * (1.0f/EMBED) - mean*mean;
    const float rstd = rsqrtf(var + LN_EPS);
    const float4 g4 = reinterpret_cast<const float4*>(gamma)[tid];
    const float4 b4 = reinterpret_cast<const float4*>(beta )[tid];
    float o[4];
    o[0] = (v.x - mean)*rstd*g4.x + b4.x;
    o[1] = (v.y - mean)*rstd*g4.y + b4.y;
    o[2] = (v.z - mean)*rstd*g4.z + b4.z;
    o[3] = (v.w - mean)*rstd*g4.w + b4.w;
    bf16 hh[4], ll[4];
    #pragma unroll
    for (int i = 0; i < 4; i++) bf16_split(o[i], hh[i], ll[i]);
    const long base = (long)row*EMBED + tid*4;
    *reinterpret_cast<__nv_bfloat162*>(oh + base + 0) = __nv_bfloat162(hh[0], hh[1]);
    *reinterpret_cast<__nv_bfloat162*>(oh + base + 2) = __nv_bfloat162(hh[2], hh[3]);
    *reinterpret_cast<__nv_bfloat162*>(ol + base + 0) = __nv_bfloat162(ll[0], ll[1]);
    *reinterpret_cast<__nv_bfloat162*>(ol + base + 2) = __nv_bfloat162(ll[2], ll[3]);
}

// ---------------- bf16x3 tensor-core GEMM, one-sync 2-stage pipeline -------
template<int BM,int BN,int WMW,int WNW,int EPI>
__global__ void __launch_bounds__(WMW*WNW*32)
tcgemm(const bf16* __restrict__ Ah_, const bf16* __restrict__ Al_,
       const bf16* __restrict__ Bh_, const bf16* __restrict__ Bl_,
       const float* __restrict__ bias, const float* __restrict__ res,
       float* __restrict__ Df, bf16* __restrict__ Dh, bf16* __restrict__ Dl,
       bf16* __restrict__ Vh, bf16* __restrict__ Vl,
       int M, int N, int K, int lda, int ldb, int ldd,
       float alpha)
{
    constexpr int BK  = 32;
    constexpr int BKP = 40;
    constexpr int THREADS = WMW*WNW*32;
    constexpr int WM = BM/WMW, WN = BN/WNW;
    constexpr int M_T = WM/16, N_T = WN/8;
    constexpr int AS = BM*BKP, BS = BN*BKP;
    constexpr int STAGE = 2*AS + 2*BS;

    extern __shared__ bf16 dsm[];

    const int tid  = threadIdx.x;
    const int lane = tid & 31;
    const int wid  = tid >> 5;
    const int wn   = wid % WNW;
    const int wm   = wid / WNW;
    const int laneRow = (lane & 7) + ((lane >> 3) & 1) * 8;
    const int laneKof = (lane >> 4) * 8;

    const int m0 = blockIdx.y * BM;
    const int n0 = blockIdx.x * BN;

    float acc[M_T][N_T][4];
    #pragma unroll
    for (int i = 0; i < M_T; i++)
        #pragma unroll
        for (int j = 0; j < N_T; j++)
            #pragma unroll
            for (int c = 0; c < 4; c++) acc[i][j][c] = 0.f;

    const int nk = K / BK;

    auto load_tile = [&](int st, int kt){
        const int k0 = kt * BK;
        bf16* sAh = dsm + st*STAGE;
        bf16* sAl = sAh + AS;
        bf16* sBh = sAl + AS;
        bf16* sBl = sBh + BS;
        #pragma unroll
        for (int t = 0; t < (BM*4 + THREADS - 1)/THREADS; t++) {
            const int idx = tid + t*THREADS;
            if (idx < BM*4) {
                const int row = idx >> 2, c = idx & 3;
                const int gr = m0 + row;
                const bool ok = gr < M;
                const long go = (long)(ok ? gr : 0)*lda + k0 + c*8;
                cp16(smaddr(sAh + row*BKP + c*8), Ah_ + go, ok);
                cp16(smaddr(sAl + row*BKP + c*8), Al_ + go, ok);
            }
        }
        #pragma unroll
        for (int t = 0; t < (BN*4 + THREADS - 1)/THREADS; t++) {
            const int idx = tid + t*THREADS;
            if (idx < BN*4) {
                const int row = idx >> 2, c = idx & 3;
                const int gn = n0 + row;
                const bool ok = gn < N;
                const long go = (long)(ok ? gn : 0)*ldb + k0 + c*8;
                cp16(smaddr(sBh + row*BKP + c*8), Bh_ + go, ok);
                cp16(smaddr(sBl + row*BKP + c*8), Bl_ + go, ok);
            }
        }
    };

    load_tile(0, 0);
    CP_COMMIT();

    for (int kt = 0; kt < nk; kt++) {
        // tile kt arrived (it is the only outstanding group at this point)
        CP_WAIT0();
        __syncthreads();    // publishes tile kt; also retires consumers of kt-1

        // prefetch kt+1 into the buffer freed by kt-1 (overlaps compute below)
        if (kt + 1 < nk) { load_tile((kt+1)&1, kt+1); CP_COMMIT(); }

        const int st = kt & 1;
        const bf16* sAh = dsm + st*STAGE;
        const bf16* sAl = sAh + AS;
        const bf16* sBh = sAl + AS;
        const bf16* sBl = sBh + BS;

        #pragma unroll
        for (int ks = 0; ks < 2; ks++) {
            const int kcb = ks*16 + laneKof;
            uint32_t bh[N_T][2], bl[N_T][2];
            #pragma unroll
            for (int p = 0; p < N_T/2; p++) {
                uint32_t r0, r1, r2, r3;
                LDSM4(r0, r1, r2, r3,
                      smaddr(sBh + (wn*WN + p*16 + laneRow)*BKP + kcb));
                bh[2*p][0]=r0; bh[2*p+1][0]=r1; bh[2*p][1]=r2; bh[2*p+1][1]=r3;
                LDSM4(r0, r1, r2, r3,
                      smaddr(sBl + (wn*WN + p*16 + laneRow)*BKP + kcb));
                bl[2*p][0]=r0; bl[2*p+1][0]=r1; bl[2*p][1]=r2; bl[2*p+1][1]=r3;
            }
            #pragma unroll
            for (int i = 0; i < M_T; i++) {
                uint32_t ah[4], al[4];
                LDSM4(ah[0], ah[1], ah[2], ah[3],
                      smaddr(sAh + (wm*WM + i*16 + laneRow)*BKP + kcb));
                LDSM4(al[0], al[1], al[2], al[3],
                      smaddr(sAl + (wm*WM + i*16 + laneRow)*BKP + kcb));
                #pragma unroll
                for (int j = 0; j < N_T; j++) {
                    MMA_BF16(acc[i][j], ah, bh[j]);
                    MMA_BF16(acc[i][j], ah, bl[j]);
                    MMA_BF16(acc[i][j], al, bh[j]);
                }
            }
        }
    }

    // ---- epilogue ----
    #pragma unroll
    for (int i = 0; i < M_T; i++) {
        #pragma unroll
        for (int j = 0; j < N_T; j++) {
            #pragma unroll
            for (int h2 = 0; h2 < 2; h2++) {
                const int m = m0 + wm*WM + i*16 + (lane >> 2) + h2*8;
                const int n = n0 + wn*WN + j*8  + (lane & 3)*2;
                if (m >= M || n >= N) continue;
                const float v0 = acc[i][j][h2*2 + 0];
                const float v1 = acc[i][j][h2*2 + 1];
                if (EPI == 1) {
                    const long o = (long)m*ldd + n;
                    float2 r = *reinterpret_cast<const float2*>(res + o);
                    float2 w = make_float2(v0 + bias[n] + r.x, v1 + bias[n+1] + r.y);
                    *reinterpret_cast<float2*>(Df + o) = w;
                } else if (EPI == 2) {
                    const float g0 = v0 + bias[n],   g1 = v1 + bias[n+1];
                    const float e0 = 0.5f*g0*(1.0f + erff(g0*0.70710678118654752f));
                    const float e1 = 0.5f*g1*(1.0f + erff(g1*0.70710678118654752f));
                    bf16 h0,l0,h1,l1; bf16_split(e0,h0,l0); bf16_split(e1,h1,l1);
                    const long o = (long)m*ldd + n;
                    *reinterpret_cast<__nv_bfloat162*>(Dh + o) = __nv_bfloat162(h0, h1);
                    *reinterpret_cast<__nv_bfloat162*>(Dl + o) = __nv_bfloat162(l0, l1);
                } else if (EPI == 3) {
                    bf16 h0,l0,h1,l1; bf16_split(v0,h0,l0); bf16_split(v1,h1,l1);
                    if (n < 2048) {
                        const long o = (long)m*2048 + n;
                        *reinterpret_cast<__nv_bfloat162*>(Dh + o) = __nv_bfloat162(h0, h1);
                        *reinterpret_cast<__nv_bfloat162*>(Dl + o) = __nv_bfloat162(l0, l1);
                    } else {
                        const int b_ = m / SEQ, s_ = m % SEQ;
                        const int c0 = n - 2048;
                        const long o0 = (((long)(b_*NHEADS + (c0 >> 6)))*HDIM + (c0 & 63))*SEQP + s_;
                        const long o1 = (((long)(b_*NHEADS + ((c0+1) >> 6)))*HDIM + ((c0+1) & 63))*SEQP + s_;
                        Vh[o0] = h0; Vl[o0] = l0;
                        Vh[o1] = h1; Vl[o1] = l1;
                    }
                }
            }
        }
    }
}

// ---------------- fused flash attention (unchanged) ------------------------
__global__ void __launch_bounds__(256)
flash_kernel(const bf16* __restrict__ qkh, const bf16* __restrict__ qkl,
             const bf16* __restrict__ vTh, const bf16* __restrict__ vTl,
             const float* __restrict__ mask,
             bf16* __restrict__ aoh, bf16* __restrict__ aol)
{
    extern __shared__ bf16 sm[];
    bf16* sQh = sm;
    bf16* sQl = sm + 128*KVP;
    bf16* sKV = sm + 2*128*KVP;
    const int SSTG = 4*64*KVP;

    const int tid = threadIdx.x, lane = tid & 31, wq = tid >> 5;
    const int laneRow = (lane & 7) + ((lane >> 3) & 1) * 8;
    const int laneKof = (lane >> 4) * 8;
    const int qt = blockIdx.x;
    const int z  = blockIdx.y;
    const int b  = z >> 4, h = z & 15;
    const int q0 = qt*128;

    #pragma unroll
    for (int t = 0; t < 4; t++) {
        const int idx = tid + t*256;
        const int r = idx >> 3, c = idx & 7;
        long grow = (long)b*SEQ + q0 + r;
        if (grow > MTOT-1) grow = MTOT-1;
        const long go = grow*2048 + h*64 + c*8;
        cp16(smaddr(sQh + r*KVP + c*8), qkh + go, true);
        cp16(smaddr(sQl + r*KVP + c*8), qkl + go, true);
    }
    auto load_kv = [&](int st, int ci){
        const int s0 = ci*SN;
        bf16* Kh = sKV + st*SSTG;
        bf16* Kl = Kh + 64*KVP;
        bf16* Vh = Kl + 64*KVP;
        bf16* Vl = Vh + 64*KVP;
        #pragma unroll
        for (int t = 0; t < 2; t++) {
            const int idx = tid + t*256;
            const int r = idx >> 3, c = idx & 7;
            long grow = (long)b*SEQ + s0 + r;
            if (grow > MTOT-1) grow = MTOT-1;
            const long go = grow*2048 + 1024 + h*64 + c*8;
            cp16(smaddr(Kh + r*KVP + c*8), qkh + go, true);
            cp16(smaddr(Kl + r*KVP + c*8), qkl + go, true);
            const long vo = ((long)z*HDIM + r)*SEQP + s0 + c*8;
            cp16(smaddr(Vh + r*KVP + c*8), vTh + vo, true);
            cp16(smaddr(Vl + r*KVP + c*8), vTl + vo, true);
        }
    };
    load_kv(0, 0);
    CP_COMMIT();

    uint32_t qfh[4][4], qfl[4][4];
    float Oacc[8][4];
    float m_run[2] = {-1e30f, -1e30f}, l_run[2] = {0.f, 0.f};
    #pragma unroll
    for (int j = 0; j < 8; j++)
        #pragma unroll
        for (int c = 0; c < 4; c++) Oacc[j][c] = 0.f;

    for (int ci = 0; ci < NCH; ci++) {
        if (ci + 1 < NCH) load_kv((ci+1)&1, ci+1);
        CP_COMMIT();
        CP_WAIT1();
        __syncthreads();

        if (ci == 0) {
            #pragma unroll
            for (int kk = 0; kk < 4; kk++) {
                const int kcb = kk*16 + laneKof;
                LDSM4(qfh[kk][0], qfh[kk][1], qfh[kk][2], qfh[kk][3],
                      smaddr(sQh + (wq*16 + laneRow)*KVP + kcb));
                LDSM4(qfl[kk][0], qfl[kk][1], qfl[kk][2], qfl[kk][3],
                      smaddr(sQl + (wq*16 + laneRow)*KVP + kcb));
            }
        }

        const int st = ci & 1;
        const bf16* Kh = sKV + st*SSTG;
        const bf16* Kl = Kh + 64*KVP;
        const bf16* Vh = Kl + 64*KVP;
        const bf16* Vl = Vh + 64*KVP;

        float S[8][4];
        #pragma unroll
        for (int j = 0; j < 8; j++)
            #pragma unroll
            for (int c = 0; c < 4; c++) S[j][c] = 0.f;
        #pragma unroll
        for (int kk = 0; kk < 4; kk++) {
            const int kcb = kk*16 + laneKof;
            #pragma unroll
            for (int jp = 0; jp < 4; jp++) {
                uint32_t h0,h1,h2,h3, l0,l1,l2,l3;
                LDSM4(h0, h1, h2, h3, smaddr(Kh + (jp*16 + laneRow)*KVP + kcb));
                LDSM4(l0, l1, l2, l3, smaddr(Kl + (jp*16 + laneRow)*KVP + kcb));
                uint32_t kb0[2] = {h0, h2}, kb1[2] = {h1, h3};
                uint32_t kl0[2] = {l0, l2}, kl1[2] = {l1, l3};
                MMA_BF16(S[2*jp],   qfh[kk], kb0);
                MMA_BF16(S[2*jp],   qfh[kk], kl0);
                MMA_BF16(S[2*jp],   qfl[kk], kb0);
                MMA_BF16(S[2*jp+1], qfh[kk], kb1);
                MMA_BF16(S[2*jp+1], qfh[kk], kl1);
                MMA_BF16(S[2*jp+1], qfl[kk], kb1);
            }
        }

        const int s_lane = ci*SN + (lane & 3)*2;
        float mx[2] = {m_run[0], m_run[1]};
        #pragma unroll
        for (int j = 0; j < 8; j++) {
            #pragma unroll
            for (int c = 0; c < 4; c++) {
                const int s  = s_lane + j*8 + (c & 1);
                const int ch = c >> 1;
                float v = S[j][c]*SCALE;
                if (s >= SEQ) v = -1e30f;
                else if (qt == 8) {
                    const int q = q0 + wq*16 + (lane >> 2) + ch*8;
                    if (q < SEQ && s < NPATCH) {
                        const float mv = mask[((long)b*NQ + (q - NPATCH))*NPATCH + s];
                        if (!(mv > 0.5f)) v = NEG_BIG;
                    }
                }
                S[j][c] = v;
                mx[ch] = fmaxf(mx[ch], v);
            }
        }
        #pragma unroll
        for (int ch = 0; ch < 2; ch++) {
            mx[ch] = fmaxf(mx[ch], __shfl_xor_sync(0xffffffffu, mx[ch], 1));
            mx[ch] = fmaxf(mx[ch], __shfl_xor_sync(0xffffffffu, mx[ch], 2));
        }
        float alpha[2], sum[2] = {0.f, 0.f};
        #pragma unroll
        for (int ch = 0; ch < 2; ch++) alpha[ch] = __expf(m_run[ch] - mx[ch]);
        m_run[0] = mx[0]; m_run[1] = mx[1];

        #pragma unroll
        for (int j = 0; j < 8; j++) {
            #pragma unroll
            for (int c = 0; c < 4; c++) {
                const float p = __expf(S[j][c] - mx[c >> 1]);
                S[j][c] = p;
                sum[c >> 1] += p;
            }
        }
        #pragma unroll
        for (int ch = 0; ch < 2; ch++) {
            sum[ch] += __shfl_xor_sync(0xffffffffu, sum[ch], 1);
            sum[ch] += __shfl_xor_sync(0xffffffffu, sum[ch], 2);
            l_run[ch] = l_run[ch]*alpha[ch] + sum[ch];
        }
        #pragma unroll
        for (int j = 0; j < 8; j++) {
            #pragma unroll
            for (int c = 0; c < 4; c++) Oacc[j][c] *= alpha[c >> 1];
        }

        #pragma unroll
        for (int kk = 0; kk < 4; kk++) {
            uint32_t pah[4], pal[4];
            #pragma unroll
            for (int half = 0; half < 2; half++) {
                const int jt = 2*kk + half;
                bf16 h0,l0,h1,l1,h2,l2,h3,l3;
                bf16_split(S[jt][0], h0, l0); bf16_split(S[jt][1], h1, l1);
                bf16_split(S[jt][2], h2, l2); bf16_split(S[jt][3], h3, l3);
                pah[0 + 2*half] = pack_bf16x2(h0, h1);
                pah[1 + 2*half] = pack_bf16x2(h2, h3);
                pal[0 + 2*half] = pack_bf16x2(l0, l1);
                pal[1 + 2*half] = pack_bf16x2(l2, l3);
            }
            const int kcb = kk*16 + laneKof;
            #pragma unroll
            for (int dp = 0; dp < 4; dp++) {
                uint32_t h0,h1,h2,h3, l0,l1,l2,l3;
                LDSM4(h0, h1, h2, h3, smaddr(Vh + (dp*16 + laneRow)*KVP + kcb));
                LDSM4(l0, l1, l2, l3, smaddr(Vl + (dp*16 + laneRow)*KVP + kcb));
                uint32_t vb0[2] = {h0, h2}, vb1[2] = {h1, h3};
                uint32_t vl0[2] = {l0, l2}, vl1[2] = {l1, l3};
                MMA_BF16(Oacc[2*dp],   pah, vb0);
                MMA_BF16(Oacc[2*dp],   pah, vl0);
                MMA_BF16(Oacc[2*dp],   pal, vb0);
                MMA_BF16(Oacc[2*dp+1], pah, vb1);
                MMA_BF16(Oacc[2*dp+1], pah, vl1);
                MMA_BF16(Oacc[2*dp+1], pal, vb1);
            }
        }
        __syncthreads();
    }

    #pragma unroll
    for (int ch = 0; ch < 2; ch++) {
        const int q = q0 + wq*16 + (lane >> 2) + ch*8;
        if (q >= SEQ) continue;
        const float inv = 1.0f / l_run[ch];
        const long rowo = ((long)b*SEQ + q)*EMBED + h*64;
        #pragma unroll
        for (int jd = 0; jd < 8; jd++) {
            const int d = jd*8 + (lane & 3)*2;
            const float v0 = Oacc[jd][ch*2 + 0]*inv;
            const float v1 = Oacc[jd][ch*2 + 1]*inv;
            bf16 h0,l0,h1,l1; bf16_split(v0,h0,l0); bf16_split(v1,h1,l1);
            *reinterpret_cast<__nv_bfloat162*>(aoh + rowo + d) = __nv_bfloat162(h0, h1);
            *reinterpret_cast<__nv_bfloat162*>(aol + rowo + d) = __nv_bfloat162(l0, l1);
        }
    }
}

// ---------------- launch ----------------
extern "C" void kernel_launch(void* const* d_in, const int* in_sizes, int n_in,
                              void* d_out, int out_size)
{
    (void)in_sizes; (void)n_in; (void)out_size;
    const float* x      = (const float*)d_in[0];
    const float* mask   = (const float*)d_in[1];
    const float* qkv_w  = (const float*)d_in[2];
    const float* proj_w = (const float*)d_in[3];
    const float* proj_b = (const float*)d_in[4];
    const float* ln1_g  = (const float*)d_in[5];
    const float* ln1_b  = (const float*)d_in[6];
    const float* ln2_g  = (const float*)d_in[7];
    const float* ln2_b  = (const float*)d_in[8];
    const float* fc1_w  = (const float*)d_in[9];
    const float* fc1_b  = (const float*)d_in[10];
    const float* fc2_w  = (const float*)d_in[11];
    const float* fc2_b  = (const float*)d_in[12];
    float* out = (float*)d_out;

    bf16 *xn_h, *xn_l, *qk_h, *qk_l, *vT_h, *vT_l, *ao_h, *ao_l, *h1_h, *h1_l;
    bf16 *wqkv_h, *wqkv_l, *wprj_h, *wprj_l, *wfc1_h, *wfc1_l, *wfc2_h, *wfc2_l;
    float *xmid;
    cudaGetSymbolAddress((void**)&xn_h, g_xn_h);   cudaGetSymbolAddress((void**)&xn_l, g_xn_l);
    cudaGetSymbolAddress((void**)&qk_h, g_qk_h);   cudaGetSymbolAddress((void**)&qk_l, g_qk_l);
    cudaGetSymbolAddress((void**)&vT_h, g_vT_h);   cudaGetSymbolAddress((void**)&vT_l, g_vT_l);
    cudaGetSymbolAddress((void**)&ao_h, g_ao_h);   cudaGetSymbolAddress((void**)&ao_l, g_ao_l);
    cudaGetSymbolAddress((void**)&h1_h, g_h1_h);   cudaGetSymbolAddress((void**)&h1_l, g_h1_l);
    cudaGetSymbolAddress((void**)&wqkv_h, g_wqkv_h); cudaGetSymbolAddress((void**)&wqkv_l, g_wqkv_l);
    cudaGetSymbolAddress((void**)&wprj_h, g_wprj_h); cudaGetSymbolAddress((void**)&wprj_l, g_wprj_l);
    cudaGetSymbolAddress((void**)&wfc1_h, g_wfc1_h); cudaGetSymbolAddress((void**)&wfc1_l, g_wfc1_l);
    cudaGetSymbolAddress((void**)&wfc2_h, g_wfc2_h); cudaGetSymbolAddress((void**)&wfc2_l, g_wfc2_l);
    cudaGetSymbolAddress((void**)&xmid,   g_xmid);

    const int SMEM_W = smem_bytes(128, 256);   // 122880 B (BM=128, BN=256)
    cudaFuncSetAttribute(tcgemm<128,256,2,8,1>, cudaFuncAttributeMaxDynamicSharedMemorySize, SMEM_W);
    cudaFuncSetAttribute(tcgemm<128,256,2,8,2>, cudaFuncAttributeMaxDynamicSharedMemorySize, SMEM_W);
    cudaFuncSetAttribute(tcgemm<128,256,2,8,3>, cudaFuncAttributeMaxDynamicSharedMemorySize, SMEM_W);
    cudaFuncSetAttribute(flash_kernel, cudaFuncAttributeMaxDynamicSharedMemorySize, FLASH_SMEM);

    const int MB = (MTOT + 127) / 128;   // 71

    wsplitT<<<dim3(3072/32, 1024/32), dim3(32,8)>>>(qkv_w,  wqkv_h, wqkv_l, 1024, 3072);
    wsplitT<<<dim3(1024/32, 1024/32), dim3(32,8)>>>(proj_w, wprj_h, wprj_l, 1024, 1024);
    wsplitT<<<dim3(4096/32, 1024/32), dim3(32,8)>>>(fc1_w,  wfc1_h, wfc1_l, 1024, 4096);
    wsplitT<<<dim3(1024/32, 4096/32), dim3(32,8)>>>(fc2_w,  wfc2_h, wfc2_l, 4096, 1024);

    ln_kernel<<<MTOT, 256>>>(x, ln1_g, ln1_b, xn_h, xn_l);

    // qkv (EPI=3): N=3072 -> 12 x 256-wide blocks
    tcgemm<128,256,2,8,3><<<dim3(3072/256, MB, 1), 512, SMEM_W>>>(
        xn_h, xn_l, wqkv_h, wqkv_l, nullptr, nullptr,
        nullptr, qk_h, qk_l, vT_h, vT_l,
        MTOT, 3072, 1024, 1024, 1024, 0, 1.0f);

    flash_kernel<<<dim3(9, BATCH*NHEADS), 256, FLASH_SMEM>>>(
        qk_h, qk_l, vT_h, vT_l, mask, ao_h, ao_l);

    // x_mid = ao @ proj + b + x (EPI=1): N=1024 -> 4 blocks
    tcgemm<128,256,2,8,1><<<dim3(EMBED/256, MB, 1), 512, SMEM_W>>>(
        ao_h, ao_l, wprj_h, wprj_l, proj_b, x,
        xmid, nullptr, nullptr, nullptr, nullptr,
        MTOT, EMBED, 1024, 1024, 1024, EMBED, 1.0f);

    ln_kernel<<<MTOT, 256>>>(xmid, ln2_g, ln2_b, xn_h, xn_l);

    // h1 = gelu(ln2 @ fc1 + b) (EPI=2): N=4096 -> 16 blocks
    tcgemm<128,256,2,8,2><<<dim3(MLPH/256, MB, 1), 512, SMEM_W>>>(
        xn_h, xn_l, wfc1_h, wfc1_l, fc1_b, nullptr,
        nullptr, h1_h, h1_l, nullptr, nullptr,
        MTOT, MLPH, 1024, 1024, 1024, MLPH, 1.0f);

    // out = h1 @ fc2 + b + xmid (EPI=1): N=1024 -> 4 blocks, K=4096
    tcgemm<128,256,2,8,1><<<dim3(EMBED/256, MB, 1), 512, SMEM_W>>>(
        h1_h, h1_l, wfc2_h, wfc2_l, fc2_b, xmid,
        out, nullptr, nullptr, nullptr, nullptr,
        MTOT, EMBED, 4096, 4096, 4096, EMBED, 1.0f);
}

// round 12
// speedup vs baseline: 1.5172x; 1.5172x over previous
#include <cuda_runtime.h>
#include <cuda_fp16.h>
#include <math.h>
#include <stdint.h>

using h16 = __half;

// ---------------- problem constants ----------------
#define EMBED   1024
#define NHEADS  16
#define HDIM    64
#define SCALE   0.125f
#define NQ      100
#define NPATCH  1024
#define SEQ     1124
#define SEQP    1152
#define BATCH   8
#define MTOT    (BATCH*SEQ)      // 8992
#define MLPH    4096
#define LN_EPS  1e-6f
#define NEG_BIG (-1.0e9f)

// smem bytes: 2 stages x (A single BM*40 + B pair 2*BN*40) elems x 2 B
constexpr int smem_bytes(int BM, int BN) {
    return 2 * (BM*40 + 2*BN*40) * 2;
}

// flash tiles
#define SN    64
#define NCH   (SEQP/SN)
#define KVP   72
constexpr int FLASH_SMEM = (128*KVP + 2*4*64*KVP) * 2;   // Q single + 2 stages (Kh,Kl,Vh,Vl)

// ---------------- scratch ----------------
__device__ h16   g_xn  [MTOT*EMBED];                       // LN out (single)
__device__ h16   g_q   [(long)MTOT*EMBED];                 // q single
__device__ h16   g_k_h [(long)MTOT*EMBED], g_k_l [(long)MTOT*EMBED];
__device__ h16   g_vT_h[(long)BATCH*NHEADS*HDIM*SEQP], g_vT_l[(long)BATCH*NHEADS*HDIM*SEQP];
__device__ h16   g_ao  [MTOT*EMBED];                       // attn out single
__device__ h16   g_h1  [(long)MTOT*MLPH];                  // mlp hidden single
__device__ float g_xmid[(long)MTOT*EMBED];
__device__ h16   g_wqkv_h[(long)3072*1024], g_wqkv_l[(long)3072*1024];
__device__ h16   g_wprj_h[(long)1024*1024], g_wprj_l[(long)1024*1024];
__device__ h16   g_wfc1_h[(long)4096*1024], g_wfc1_l[(long)4096*1024];
__device__ h16   g_wfc2_h[(long)1024*4096], g_wfc2_l[(long)1024*4096];

// ---------------- helpers ----------------
__device__ __forceinline__ void h16_split(float v, h16& h, h16& l){
    h = __float2half(v);
    l = __float2half(v - __half2float(h));
}
__device__ __forceinline__ float warpSum(float v){
    #pragma unroll
    for (int o = 16; o > 0; o >>= 1) v += __shfl_xor_sync(0xffffffffu, v, o);
    return v;
}
__device__ __forceinline__ void cp16(uint32_t s, const void* g, bool valid){
    asm volatile("cp.async.cg.shared.global [%0], [%1], 16, %2;"
                 :: "r"(s), "l"(g), "r"(valid ? 16 : 0));
}
#define CP_COMMIT() asm volatile("cp.async.commit_group;" ::: "memory")
#define CP_WAIT1()  asm volatile("cp.async.wait_group 1;" ::: "memory")
__device__ __forceinline__ uint32_t smaddr(const void* p){
    return (uint32_t)__cvta_generic_to_shared(p);
}
__device__ __forceinline__ uint32_t pack_h2(h16 a, h16 b){
    __half2 t(a, b);
    return *reinterpret_cast<uint32_t*>(&t);
}

#define MMA_F16(c, a, b) \
    asm volatile("mma.sync.aligned.m16n8k16.row.col.f32.f16.f16.f32 " \
                 "{%0,%1,%2,%3},{%4,%5,%6,%7},{%8,%9},{%0,%1,%2,%3};" \
                 : "+f"(c[0]), "+f"(c[1]), "+f"(c[2]), "+f"(c[3]) \
                 : "r"(a[0]), "r"(a[1]), "r"(a[2]), "r"(a[3]), "r"(b[0]), "r"(b[1]))

#define LDSM4(r0, r1, r2, r3, addr) \
    asm volatile("ldmatrix.sync.aligned.m8n8.x4.shared.b16 {%0,%1,%2,%3}, [%4];" \
                 : "=r"(r0), "=r"(r1), "=r"(r2), "=r"(r3) : "r"(addr))

// ---------------- weight transpose + split (fp16 pair) ----------------
__global__ void wsplitT(const float* __restrict__ w, h16* __restrict__ oh,
                        h16* __restrict__ ol, int K, int N)
{
    __shared__ float sm[32][33];
    const int n0 = blockIdx.x*32, k0 = blockIdx.y*32;
    #pragma unroll
    for (int i = 0; i < 4; i++) {
        const int k = threadIdx.y + i*8;
        sm[k][threadIdx.x] = w[(long)(k0+k)*N + n0 + threadIdx.x];
    }
    __syncthreads();
    #pragma unroll
    for (int i = 0; i < 4; i++) {
        const int nl = threadIdx.y + i*8;
        const float v = sm[threadIdx.x][nl];
        h16 h, l; h16_split(v, h, l);
        const long o = (long)(n0+nl)*K + k0 + threadIdx.x;
        oh[o] = h; ol[o] = l;
    }
}

// ---------------- LayerNorm -> single fp16 ----------------
__global__ void ln_kernel(const float* __restrict__ x,
                          const float* __restrict__ gamma,
                          const float* __restrict__ beta,
                          h16* __restrict__ oh)
{
    const int row = blockIdx.x;
    const int tid = threadIdx.x;
    const float4 v = reinterpret_cast<const float4*>(x + (size_t)row*EMBED)[tid];
    float s  = v.x + v.y + v.z + v.w;
    float ss = v.x*v.x + v.y*v.y + v.z*v.z + v.w*v.w;
    s = warpSum(s); ss = warpSum(ss);
    __shared__ float sh1[8], sh2[8];
    const int w = tid >> 5, l = tid & 31;
    if (l == 0) { sh1[w] = s; sh2[w] = ss; }
    __syncthreads();
    if (w == 0) {
        float a = (l < 8) ? sh1[l] : 0.f;
        float b = (l < 8) ? sh2[l] : 0.f;
        a = warpSum(a); b = warpSum(b);
        if (l == 0) { sh1[0] = a; sh2[0] = b; }
    }
    __syncthreads();
    const float mean = sh1[0] * (1.0f/EMBED);
    const float var  = sh2[0] * (1.0f/EMBED) - mean*mean;
    const float rstd = rsqrtf(var + LN_EPS);
    const float4 g4 = reinterpret_cast<const float4*>(gamma)[tid];
    const float4 b4 = reinterpret_cast<const float4*>(beta )[tid];
    float o[4];
    o[0] = (v.x - mean)*rstd*g4.x + b4.x;
    o[1] = (v.y - mean)*rstd*g4.y + b4.y;
    o[2] = (v.z - mean)*rstd*g4.z + b4.z;
    o[3] = (v.w - mean)*rstd*g4.w + b4.w;
    const long base = (long)row*EMBED + tid*4;
    *reinterpret_cast<__half2*>(oh + base + 0) = __half2(__float2half(o[0]), __float2half(o[1]));
    *reinterpret_cast<__half2*>(oh + base + 2) = __half2(__float2half(o[2]), __float2half(o[3]));
}

// ---------------- fp16x2 tensor-core GEMM (A single, B pair) ---------------
// EPI: 1 Df=acc+bias+res ; 2 D1=fp16(gelu(acc+bias)) ;
//      3 qkv: n<1024 -> D1=q single; n<2048 -> D2/D3 = K pair; else V^T pair D4/D5
template<int BM,int BN,int WMW,int WNW,int EPI>
__global__ void __launch_bounds__(WMW*WNW*32)
tcgemm(const h16* __restrict__ A_,
       const h16* __restrict__ Bh_, const h16* __restrict__ Bl_,
       const float* __restrict__ bias, const float* __restrict__ res,
       float* __restrict__ Df, h16* __restrict__ D1, h16* __restrict__ D2,
       h16* __restrict__ D3, h16* __restrict__ D4, h16* __restrict__ D5,
       int M, int N, int K, int lda, int ldb, int ldd)
{
    constexpr int BK  = 32;
    constexpr int BKP = 40;
    constexpr int THREADS = WMW*WNW*32;
    constexpr int WM = BM/WMW, WN = BN/WNW;
    constexpr int M_T = WM/16, N_T = WN/8;
    constexpr int AS = BM*BKP, BS = BN*BKP;
    constexpr int STAGE = AS + 2*BS;

    extern __shared__ h16 dsm[];

    const int tid  = threadIdx.x;
    const int lane = tid & 31;
    const int wid  = tid >> 5;
    const int wn   = wid % WNW;
    const int wm   = wid / WNW;
    const int laneRow = (lane & 7) + ((lane >> 3) & 1) * 8;
    const int laneKof = (lane >> 4) * 8;

    const int m0 = blockIdx.y * BM;
    const int n0 = blockIdx.x * BN;

    float acc[M_T][N_T][4];
    #pragma unroll
    for (int i = 0; i < M_T; i++)
        #pragma unroll
        for (int j = 0; j < N_T; j++)
            #pragma unroll
            for (int c = 0; c < 4; c++) acc[i][j][c] = 0.f;

    const int nk = K / BK;

    auto load_tile = [&](int st, int kt){
        const int k0 = kt * BK;
        h16* sA  = dsm + st*STAGE;
        h16* sBh = sA + AS;
        h16* sBl = sBh + BS;
        #pragma unroll
        for (int t = 0; t < (BM*4 + THREADS - 1)/THREADS; t++) {
            const int idx = tid + t*THREADS;
            if (idx < BM*4) {
                const int row = idx >> 2, c = idx & 3;
                const int gr = m0 + row;
                const bool ok = gr < M;
                const long go = (long)(ok ? gr : 0)*lda + k0 + c*8;
                cp16(smaddr(sA + row*BKP + c*8), A_ + go, ok);
            }
        }
        #pragma unroll
        for (int t = 0; t < (BN*4 + THREADS - 1)/THREADS; t++) {
            const int idx = tid + t*THREADS;
            if (idx < BN*4) {
                const int row = idx >> 2, c = idx & 3;
                const int gn = n0 + row;
                const bool ok = gn < N;
                const long go = (long)(ok ? gn : 0)*ldb + k0 + c*8;
                cp16(smaddr(sBh + row*BKP + c*8), Bh_ + go, ok);
                cp16(smaddr(sBl + row*BKP + c*8), Bl_ + go, ok);
            }
        }
    };

    load_tile(0, 0);
    CP_COMMIT();

    for (int kt = 0; kt < nk; kt++) {
        if (kt + 1 < nk) load_tile((kt+1)&1, kt+1);
        CP_COMMIT();
        CP_WAIT1();
        __syncthreads();

        const int st = kt & 1;
        const h16* sA  = dsm + st*STAGE;
        const h16* sBh = sA + AS;
        const h16* sBl = sBh + BS;

        #pragma unroll
        for (int ks = 0; ks < 2; ks++) {
            const int kcb = ks*16 + laneKof;
            uint32_t bh[N_T][2], bl[N_T][2];
            #pragma unroll
            for (int p = 0; p < N_T/2; p++) {
                uint32_t r0, r1, r2, r3;
                LDSM4(r0, r1, r2, r3,
                      smaddr(sBh + (wn*WN + p*16 + laneRow)*BKP + kcb));
                bh[2*p][0]=r0; bh[2*p+1][0]=r1; bh[2*p][1]=r2; bh[2*p+1][1]=r3;
                LDSM4(r0, r1, r2, r3,
                      smaddr(sBl + (wn*WN + p*16 + laneRow)*BKP + kcb));
                bl[2*p][0]=r0; bl[2*p+1][0]=r1; bl[2*p][1]=r2; bl[2*p+1][1]=r3;
            }
            #pragma unroll
            for (int i = 0; i < M_T; i++) {
                uint32_t a[4];
                LDSM4(a[0], a[1], a[2], a[3],
                      smaddr(sA + (wm*WM + i*16 + laneRow)*BKP + kcb));
                #pragma unroll
                for (int j = 0; j < N_T; j++) {
                    MMA_F16(acc[i][j], a, bh[j]);
                    MMA_F16(acc[i][j], a, bl[j]);
                }
            }
        }
        __syncthreads();
    }

    // ---- epilogue ----
    #pragma unroll
    for (int i = 0; i < M_T; i++) {
        #pragma unroll
        for (int j = 0; j < N_T; j++) {
            #pragma unroll
            for (int h2 = 0; h2 < 2; h2++) {
                const int m = m0 + wm*WM + i*16 + (lane >> 2) + h2*8;
                const int n = n0 + wn*WN + j*8  + (lane & 3)*2;
                if (m >= M || n >= N) continue;
                const float v0 = acc[i][j][h2*2 + 0];
                const float v1 = acc[i][j][h2*2 + 1];
                if (EPI == 1) {
                    const long o = (long)m*ldd + n;
                    float2 r = *reinterpret_cast<const float2*>(res + o);
                    float2 w = make_float2(v0 + bias[n] + r.x, v1 + bias[n+1] + r.y);
                    *reinterpret_cast<float2*>(Df + o) = w;
                } else if (EPI == 2) {
                    const float g0 = v0 + bias[n],   g1 = v1 + bias[n+1];
                    const float e0 = 0.5f*g0*(1.0f + erff(g0*0.70710678118654752f));
                    const float e1 = 0.5f*g1*(1.0f + erff(g1*0.70710678118654752f));
                    const long o = (long)m*ldd + n;
                    *reinterpret_cast<__half2*>(D1 + o) =
                        __half2(__float2half(e0), __float2half(e1));
                } else if (EPI == 3) {
                    if (n < 1024) {
                        const long o = (long)m*1024 + n;
                        *reinterpret_cast<__half2*>(D1 + o) =
                            __half2(__float2half(v0), __float2half(v1));
                    } else if (n < 2048) {
                        h16 h0,l0,h1,l1; h16_split(v0,h0,l0); h16_split(v1,h1,l1);
                        const long o = (long)m*1024 + (n - 1024);
                        *reinterpret_cast<__half2*>(D2 + o) = __half2(h0, h1);
                        *reinterpret_cast<__half2*>(D3 + o) = __half2(l0, l1);
                    } else {
                        h16 h0,l0,h1,l1; h16_split(v0,h0,l0); h16_split(v1,h1,l1);
                        const int b_ = m / SEQ, s_ = m % SEQ;
                        const int c0 = n - 2048;
                        const long o0 = (((long)(b_*NHEADS + (c0 >> 6)))*HDIM + (c0 & 63))*SEQP + s_;
                        const long o1 = (((long)(b_*NHEADS + ((c0+1) >> 6)))*HDIM + ((c0+1) & 63))*SEQP + s_;
                        D4[o0] = h0; D5[o0] = l0;
                        D4[o1] = h1; D5[o1] = l1;
                    }
                }
            }
        }
    }
}

// ---------------- fused flash attention (fp16x2) ---------------------------
__global__ void __launch_bounds__(256)
flash_kernel(const h16* __restrict__ q_, const h16* __restrict__ kh_,
             const h16* __restrict__ kl_,
             const h16* __restrict__ vTh, const h16* __restrict__ vTl,
             const float* __restrict__ mask,
             h16* __restrict__ ao)
{
    extern __shared__ h16 sm[];
    h16* sQ  = sm;
    h16* sKV = sm + 128*KVP;
    const int SSTG = 4*64*KVP;

    const int tid = threadIdx.x, lane = tid & 31, wq = tid >> 5;
    const int laneRow = (lane & 7) + ((lane >> 3) & 1) * 8;
    const int laneKof = (lane >> 4) * 8;
    const int qt = blockIdx.x;
    const int z  = blockIdx.y;
    const int b  = z >> 4, h = z & 15;
    const int q0 = qt*128;

    #pragma unroll
    for (int t = 0; t < 4; t++) {
        const int idx = tid + t*256;
        const int r = idx >> 3, c = idx & 7;
        long grow = (long)b*SEQ + q0 + r;
        if (grow > MTOT-1) grow = MTOT-1;
        cp16(smaddr(sQ + r*KVP + c*8), q_ + grow*1024 + h*64 + c*8, true);
    }
    auto load_kv = [&](int st, int ci){
        const int s0 = ci*SN;
        h16* Kh = sKV + st*SSTG;
        h16* Kl = Kh + 64*KVP;
        h16* Vh = Kl + 64*KVP;
        h16* Vl = Vh + 64*KVP;
        #pragma unroll
        for (int t = 0; t < 2; t++) {
            const int idx = tid + t*256;
            const int r = idx >> 3, c = idx & 7;
            long grow = (long)b*SEQ + s0 + r;
            if (grow > MTOT-1) grow = MTOT-1;
            const long go = grow*1024 + h*64 + c*8;
            cp16(smaddr(Kh + r*KVP + c*8), kh_ + go, true);
            cp16(smaddr(Kl + r*KVP + c*8), kl_ + go, true);
            const long vo = ((long)z*HDIM + r)*SEQP + s0 + c*8;
            cp16(smaddr(Vh + r*KVP + c*8), vTh + vo, true);
            cp16(smaddr(Vl + r*KVP + c*8), vTl + vo, true);
        }
    };
    load_kv(0, 0);
    CP_COMMIT();

    uint32_t qf[4][4];
    float Oacc[8][4];
    float m_run[2] = {-1e30f, -1e30f}, l_run[2] = {0.f, 0.f};
    #pragma unroll
    for (int j = 0; j < 8; j++)
        #pragma unroll
        for (int c = 0; c < 4; c++) Oacc[j][c] = 0.f;

    for (int ci = 0; ci < NCH; ci++) {
        if (ci + 1 < NCH) load_kv((ci+1)&1, ci+1);
        CP_COMMIT();
        CP_WAIT1();
        __syncthreads();

        if (ci == 0) {
            #pragma unroll
            for (int kk = 0; kk < 4; kk++) {
                const int kcb = kk*16 + laneKof;
                LDSM4(qf[kk][0], qf[kk][1], qf[kk][2], qf[kk][3],
                      smaddr(sQ + (wq*16 + laneRow)*KVP + kcb));
            }
        }

        const int st = ci & 1;
        const h16* Kh = sKV + st*SSTG;
        const h16* Kl = Kh + 64*KVP;
        const h16* Vh = Kl + 64*KVP;
        const h16* Vl = Vh + 64*KVP;

        // ---- S = Q (Kh + Kl)^T ----
        float S[8][4];
        #pragma unroll
        for (int j = 0; j < 8; j++)
            #pragma unroll
            for (int c = 0; c < 4; c++) S[j][c] = 0.f;
        #pragma unroll
        for (int kk = 0; kk < 4; kk++) {
            const int kcb = kk*16 + laneKof;
            #pragma unroll
            for (int jp = 0; jp < 4; jp++) {
                uint32_t h0,h1,h2,h3, l0,l1,l2,l3;
                LDSM4(h0, h1, h2, h3, smaddr(Kh + (jp*16 + laneRow)*KVP + kcb));
                LDSM4(l0, l1, l2, l3, smaddr(Kl + (jp*16 + laneRow)*KVP + kcb));
                uint32_t kb0[2] = {h0, h2}, kb1[2] = {h1, h3};
                uint32_t kl0[2] = {l0, l2}, kl1[2] = {l1, l3};
                MMA_F16(S[2*jp],   qf[kk], kb0);
                MMA_F16(S[2*jp],   qf[kk], kl0);
                MMA_F16(S[2*jp+1], qf[kk], kb1);
                MMA_F16(S[2*jp+1], qf[kk], kl1);
            }
        }

        const int s_lane = ci*SN + (lane & 3)*2;
        float mx[2] = {m_run[0], m_run[1]};
        #pragma unroll
        for (int j = 0; j < 8; j++) {
            #pragma unroll
            for (int c = 0; c < 4; c++) {
                const int s  = s_lane + j*8 + (c & 1);
                const int ch = c >> 1;
                float v = S[j][c]*SCALE;
                if (s >= SEQ) v = -1e30f;
                else if (qt == 8) {
                    const int q = q0 + wq*16 + (lane >> 2) + ch*8;
                    if (q < SEQ && s < NPATCH) {
                        const float mv = mask[((long)b*NQ + (q - NPATCH))*NPATCH + s];
                        if (!(mv > 0.5f)) v = NEG_BIG;
                    }
                }
                S[j][c] = v;
                mx[ch] = fmaxf(mx[ch], v);
            }
        }
        #pragma unroll
        for (int ch = 0; ch < 2; ch++) {
            mx[ch] = fmaxf(mx[ch], __shfl_xor_sync(0xffffffffu, mx[ch], 1));
            mx[ch] = fmaxf(mx[ch], __shfl_xor_sync(0xffffffffu, mx[ch], 2));
        }
        float alpha[2], sum[2] = {0.f, 0.f};
        #pragma unroll
        for (int ch = 0; ch < 2; ch++) alpha[ch] = __expf(m_run[ch] - mx[ch]);
        m_run[0] = mx[0]; m_run[1] = mx[1];

        #pragma unroll
        for (int j = 0; j < 8; j++) {
            #pragma unroll
            for (int c = 0; c < 4; c++) {
                const float p = __expf(S[j][c] - mx[c >> 1]);
                S[j][c] = p;
                sum[c >> 1] += p;
            }
        }
        #pragma unroll
        for (int ch = 0; ch < 2; ch++) {
            sum[ch] += __shfl_xor_sync(0xffffffffu, sum[ch], 1);
            sum[ch] += __shfl_xor_sync(0xffffffffu, sum[ch], 2);
            l_run[ch] = l_run[ch]*alpha[ch] + sum[ch];
        }
        #pragma unroll
        for (int j = 0; j < 8; j++) {
            #pragma unroll
            for (int c = 0; c < 4; c++) Oacc[j][c] *= alpha[c >> 1];
        }

        // ---- O += P (Vh + Vl) ----
        #pragma unroll
        for (int kk = 0; kk < 4; kk++) {
            uint32_t pa[4];
            #pragma unroll
            for (int half = 0; half < 2; half++) {
                const int jt = 2*kk + half;
                pa[0 + 2*half] = pack_h2(__float2half(S[jt][0]), __float2half(S[jt][1]));
                pa[1 + 2*half] = pack_h2(__float2half(S[jt][2]), __float2half(S[jt][3]));
            }
            const int kcb = kk*16 + laneKof;
            #pragma unroll
            for (int dp = 0; dp < 4; dp++) {
                uint32_t h0,h1,h2,h3, l0,l1,l2,l3;
                LDSM4(h0, h1, h2, h3, smaddr(Vh + (dp*16 + laneRow)*KVP + kcb));
                LDSM4(l0, l1, l2, l3, smaddr(Vl + (dp*16 + laneRow)*KVP + kcb));
                uint32_t vb0[2] = {h0, h2}, vb1[2] = {h1, h3};
                uint32_t vl0[2] = {l0, l2}, vl1[2] = {l1, l3};
                MMA_F16(Oacc[2*dp],   pa, vb0);
                MMA_F16(Oacc[2*dp],   pa, vl0);
                MMA_F16(Oacc[2*dp+1], pa, vb1);
                MMA_F16(Oacc[2*dp+1], pa, vl1);
            }
        }
        __syncthreads();
    }

    #pragma unroll
    for (int ch = 0; ch < 2; ch++) {
        const int q = q0 + wq*16 + (lane >> 2) + ch*8;
        if (q >= SEQ) continue;
        const float inv = 1.0f / l_run[ch];
        const long rowo = ((long)b*SEQ + q)*EMBED + h*64;
        #pragma unroll
        for (int jd = 0; jd < 8; jd++) {
            const int d = jd*8 + (lane & 3)*2;
            *reinterpret_cast<__half2*>(ao + rowo + d) =
                __half2(__float2half(Oacc[jd][ch*2 + 0]*inv),
                        __float2half(Oacc[jd][ch*2 + 1]*inv));
        }
    }
}

// ---------------- launch ----------------
extern "C" void kernel_launch(void* const* d_in, const int* in_sizes, int n_in,
                              void* d_out, int out_size)
{
    (void)in_sizes; (void)n_in; (void)out_size;
    const float* x      = (const float*)d_in[0];
    const float* mask   = (const float*)d_in[1];
    const float* qkv_w  = (const float*)d_in[2];
    const float* proj_w = (const float*)d_in[3];
    const float* proj_b = (const float*)d_in[4];
    const float* ln1_g  = (const float*)d_in[5];
    const float* ln1_b  = (const float*)d_in[6];
    const float* ln2_g  = (const float*)d_in[7];
    const float* ln2_b  = (const float*)d_in[8];
    const float* fc1_w  = (const float*)d_in[9];
    const float* fc1_b  = (const float*)d_in[10];
    const float* fc2_w  = (const float*)d_in[11];
    const float* fc2_b  = (const float*)d_in[12];
    float* out = (float*)d_out;

    h16 *xn, *q, *k_h, *k_l, *vT_h, *vT_l, *ao, *h1;
    h16 *wqkv_h, *wqkv_l, *wprj_h, *wprj_l, *wfc1_h, *wfc1_l, *wfc2_h, *wfc2_l;
    float *xmid;
    cudaGetSymbolAddress((void**)&xn, g_xn);
    cudaGetSymbolAddress((void**)&q, g_q);
    cudaGetSymbolAddress((void**)&k_h, g_k_h);     cudaGetSymbolAddress((void**)&k_l, g_k_l);
    cudaGetSymbolAddress((void**)&vT_h, g_vT_h);   cudaGetSymbolAddress((void**)&vT_l, g_vT_l);
    cudaGetSymbolAddress((void**)&ao, g_ao);
    cudaGetSymbolAddress((void**)&h1, g_h1);
    cudaGetSymbolAddress((void**)&wqkv_h, g_wqkv_h); cudaGetSymbolAddress((void**)&wqkv_l, g_wqkv_l);
    cudaGetSymbolAddress((void**)&wprj_h, g_wprj_h); cudaGetSymbolAddress((void**)&wprj_l, g_wprj_l);
    cudaGetSymbolAddress((void**)&wfc1_h, g_wfc1_h); cudaGetSymbolAddress((void**)&wfc1_l, g_wfc1_l);
    cudaGetSymbolAddress((void**)&wfc2_h, g_wfc2_h); cudaGetSymbolAddress((void**)&wfc2_l, g_wfc2_l);
    cudaGetSymbolAddress((void**)&xmid,   g_xmid);

    const int SMEM_G = smem_bytes(128, 128);   // 61440 B
    cudaFuncSetAttribute(tcgemm<128,128,2,4,1>, cudaFuncAttributeMaxDynamicSharedMemorySize, SMEM_G);
    cudaFuncSetAttribute(tcgemm<128,128,2,4,2>, cudaFuncAttributeMaxDynamicSharedMemorySize, SMEM_G);
    cudaFuncSetAttribute(tcgemm<128,128,2,4,3>, cudaFuncAttributeMaxDynamicSharedMemorySize, SMEM_G);
    cudaFuncSetAttribute(flash_kernel, cudaFuncAttributeMaxDynamicSharedMemorySize, FLASH_SMEM);

    const int MB = (MTOT + 127) / 128;   // 71

    wsplitT<<<dim3(3072/32, 1024/32), dim3(32,8)>>>(qkv_w,  wqkv_h, wqkv_l, 1024, 3072);
    wsplitT<<<dim3(1024/32, 1024/32), dim3(32,8)>>>(proj_w, wprj_h, wprj_l, 1024, 1024);
    wsplitT<<<dim3(4096/32, 1024/32), dim3(32,8)>>>(fc1_w,  wfc1_h, wfc1_l, 1024, 4096);
    wsplitT<<<dim3(1024/32, 4096/32), dim3(32,8)>>>(fc2_w,  wfc2_h, wfc2_l, 4096, 1024);

    ln_kernel<<<MTOT, 256>>>(x, ln1_g, ln1_b, xn);

    // qkv (EPI=3): q single / K pair / V^T pair
    tcgemm<128,128,2,4,3><<<dim3(3072/128, MB, 1), 256, SMEM_G>>>(
        xn, wqkv_h, wqkv_l, nullptr, nullptr,
        nullptr, q, k_h, k_l, vT_h, vT_l,
        MTOT, 3072, 1024, 1024, 1024, 0);

    flash_kernel<<<dim3(9, BATCH*NHEADS), 256, FLASH_SMEM>>>(
        q, k_h, k_l, vT_h, vT_l, mask, ao);

    // x_mid = ao @ proj + b + x (EPI=1)
    tcgemm<128,128,2,4,1><<<dim3(EMBED/128, MB, 1), 256, SMEM_G>>>(
        ao, wprj_h, wprj_l, proj_b, x,
        xmid, nullptr, nullptr, nullptr, nullptr, nullptr,
        MTOT, EMBED, 1024, 1024, 1024, EMBED);

    ln_kernel<<<MTOT, 256>>>(xmid, ln2_g, ln2_b, xn);

    // h1 = gelu(ln2 @ fc1 + b) (EPI=2)
    tcgemm<128,128,2,4,2><<<dim3(MLPH/128, MB, 1), 256, SMEM_G>>>(
        xn, wfc1_h, wfc1_l, fc1_b, nullptr,
        nullptr, h1, nullptr, nullptr, nullptr, nullptr,
        MTOT, MLPH, 1024, 1024, 1024, MLPH);

    // out = h1 @ fc2 + b + xmid (EPI=1)
    tcgemm<128,128,2,4,1><<<dim3(EMBED/128, MB, 1), 256, SMEM_G>>>(
        h1, wfc2_h, wfc2_l, fc2_b, xmid,
        out, nullptr, nullptr, nullptr, nullptr, nullptr,
        MTOT, EMBED, 4096, 4096, 4096, EMBED);
}

// round 13
// speedup vs baseline: 2.2703x; 1.4964x over previous
#include <cuda_runtime.h>
#include <cuda_fp16.h>
#include <math.h>
#include <stdint.h>

using h16 = __half;

// ---------------- problem constants ----------------
#define EMBED   1024
#define NHEADS  16
#define HDIM    64
#define SCALE   0.125f
#define NQ      100
#define NPATCH  1024
#define SEQ     1124
#define SEQP    1152
#define BATCH   8
#define MTOT    (BATCH*SEQ)      // 8992
#define MLPH    4096
#define LN_EPS  1e-6f
#define NEG_BIG (-1.0e9f)

// smem bytes: 2 stages x (A BM*40 + B BN*40) elems x 2 B
constexpr int smem_bytes(int BM, int BN) {
    return 2 * (BM*40 + BN*40) * 2;
}

// flash tiles
#define SN    64
#define NCH   (SEQP/SN)
#define KVP   72
constexpr int FLASH_SMEM = (128*KVP + 2*2*64*KVP) * 2;   // Q + 2 stages (K,V)

// ---------------- scratch ----------------
__device__ h16   g_xn  [MTOT*EMBED];
__device__ h16   g_q   [(long)MTOT*EMBED];
__device__ h16   g_k   [(long)MTOT*EMBED];
__device__ h16   g_vT  [(long)BATCH*NHEADS*HDIM*SEQP];
__device__ h16   g_ao  [MTOT*EMBED];
__device__ h16   g_h1  [(long)MTOT*MLPH];
__device__ float g_xmid[(long)MTOT*EMBED];
__device__ h16   g_wqkv[(long)3072*1024];
__device__ h16   g_wprj[(long)1024*1024];
__device__ h16   g_wfc1[(long)4096*1024];
__device__ h16   g_wfc2[(long)1024*4096];

// ---------------- helpers ----------------
__device__ __forceinline__ float warpSum(float v){
    #pragma unroll
    for (int o = 16; o > 0; o >>= 1) v += __shfl_xor_sync(0xffffffffu, v, o);
    return v;
}
__device__ __forceinline__ void cp16(uint32_t s, const void* g, bool valid){
    asm volatile("cp.async.cg.shared.global [%0], [%1], 16, %2;"
                 :: "r"(s), "l"(g), "r"(valid ? 16 : 0));
}
#define CP_COMMIT() asm volatile("cp.async.commit_group;" ::: "memory")
#define CP_WAIT1()  asm volatile("cp.async.wait_group 1;" ::: "memory")
__device__ __forceinline__ uint32_t smaddr(const void* p){
    return (uint32_t)__cvta_generic_to_shared(p);
}
__device__ __forceinline__ uint32_t pack_h2(h16 a, h16 b){
    __half2 t(a, b);
    return *reinterpret_cast<uint32_t*>(&t);
}

#define MMA_F16(c, a, b) \
    asm volatile("mma.sync.aligned.m16n8k16.row.col.f32.f16.f16.f32 " \
                 "{%0,%1,%2,%3},{%4,%5,%6,%7},{%8,%9},{%0,%1,%2,%3};" \
                 : "+f"(c[0]), "+f"(c[1]), "+f"(c[2]), "+f"(c[3]) \
                 : "r"(a[0]), "r"(a[1]), "r"(a[2]), "r"(a[3]), "r"(b[0]), "r"(b[1]))

#define LDSM4(r0, r1, r2, r3, addr) \
    asm volatile("ldmatrix.sync.aligned.m8n8.x4.shared.b16 {%0,%1,%2,%3}, [%4];" \
                 : "=r"(r0), "=r"(r1), "=r"(r2), "=r"(r3) : "r"(addr))

// ---------------- weight transpose to fp16: w[K][N] -> o[N][K] -------------
__global__ void wsplitT(const float* __restrict__ w, h16* __restrict__ o,
                        int K, int N)
{
    __shared__ float sm[32][33];
    const int n0 = blockIdx.x*32, k0 = blockIdx.y*32;
    #pragma unroll
    for (int i = 0; i < 4; i++) {
        const int k = threadIdx.y + i*8;
        sm[k][threadIdx.x] = w[(long)(k0+k)*N + n0 + threadIdx.x];
    }
    __syncthreads();
    #pragma unroll
    for (int i = 0; i < 4; i++) {
        const int nl = threadIdx.y + i*8;
        o[(long)(n0+nl)*K + k0 + threadIdx.x] = __float2half(sm[threadIdx.x][nl]);
    }
}

// ---------------- LayerNorm -> fp16 ----------------
__global__ void ln_kernel(const float* __restrict__ x,
                          const float* __restrict__ gamma,
                          const float* __restrict__ beta,
                          h16* __restrict__ oh)
{
    const int row = blockIdx.x;
    const int tid = threadIdx.x;
    const float4 v = reinterpret_cast<const float4*>(x + (size_t)row*EMBED)[tid];
    float s  = v.x + v.y + v.z + v.w;
    float ss = v.x*v.x + v.y*v.y + v.z*v.z + v.w*v.w;
    s = warpSum(s); ss = warpSum(ss);
    __shared__ float sh1[8], sh2[8];
    const int w = tid >> 5, l = tid & 31;
    if (l == 0) { sh1[w] = s; sh2[w] = ss; }
    __syncthreads();
    if (w == 0) {
        float a = (l < 8) ? sh1[l] : 0.f;
        float b = (l < 8) ? sh2[l] : 0.f;
        a = warpSum(a); b = warpSum(b);
        if (l == 0) { sh1[0] = a; sh2[0] = b; }
    }
    __syncthreads();
    const float mean = sh1[0] * (1.0f/EMBED);
    const float var  = sh2[0] * (1.0f/EMBED) - mean*mean;
    const float rstd = rsqrtf(var + LN_EPS);
    const float4 g4 = reinterpret_cast<const float4*>(gamma)[tid];
    const float4 b4 = reinterpret_cast<const float4*>(beta )[tid];
    float o[4];
    o[0] = (v.x - mean)*rstd*g4.x + b4.x;
    o[1] = (v.y - mean)*rstd*g4.y + b4.y;
    o[2] = (v.z - mean)*rstd*g4.z + b4.z;
    o[3] = (v.w - mean)*rstd*g4.w + b4.w;
    const long base = (long)row*EMBED + tid*4;
    *reinterpret_cast<__half2*>(oh + base + 0) = __half2(__float2half(o[0]), __float2half(o[1]));
    *reinterpret_cast<__half2*>(oh + base + 2) = __half2(__float2half(o[2]), __float2half(o[3]));
}

// ---------------- fp16 tensor-core GEMM ------------------------------------
// EPI: 1 Df=acc+bias+res ; 2 D1=fp16(gelu(acc+bias)) ;
//      3 qkv: n<1024 -> D1=q; n<2048 -> D2=k; else D3=vT (transposed)
template<int BM,int BN,int WMW,int WNW,int EPI>
__global__ void __launch_bounds__(WMW*WNW*32)
tcgemm(const h16* __restrict__ A_, const h16* __restrict__ B_,
       const float* __restrict__ bias, const float* __restrict__ res,
       float* __restrict__ Df, h16* __restrict__ D1, h16* __restrict__ D2,
       h16* __restrict__ D3,
       int M, int N, int K, int lda, int ldb, int ldd)
{
    constexpr int BK  = 32;
    constexpr int BKP = 40;
    constexpr int THREADS = WMW*WNW*32;
    constexpr int WM = BM/WMW, WN = BN/WNW;
    constexpr int M_T = WM/16, N_T = WN/8;
    constexpr int AS = BM*BKP, BS = BN*BKP;
    constexpr int STAGE = AS + BS;

    extern __shared__ h16 dsm[];

    const int tid  = threadIdx.x;
    const int lane = tid & 31;
    const int wid  = tid >> 5;
    const int wn   = wid % WNW;
    const int wm   = wid / WNW;
    const int laneRow = (lane & 7) + ((lane >> 3) & 1) * 8;
    const int laneKof = (lane >> 4) * 8;

    const int m0 = blockIdx.y * BM;
    const int n0 = blockIdx.x * BN;

    float acc[M_T][N_T][4];
    #pragma unroll
    for (int i = 0; i < M_T; i++)
        #pragma unroll
        for (int j = 0; j < N_T; j++)
            #pragma unroll
            for (int c = 0; c < 4; c++) acc[i][j][c] = 0.f;

    const int nk = K / BK;

    auto load_tile = [&](int st, int kt){
        const int k0 = kt * BK;
        h16* sA = dsm + st*STAGE;
        h16* sB = sA + AS;
        #pragma unroll
        for (int t = 0; t < (BM*4 + THREADS - 1)/THREADS; t++) {
            const int idx = tid + t*THREADS;
            if (idx < BM*4) {
                const int row = idx >> 2, c = idx & 3;
                const int gr = m0 + row;
                const bool ok = gr < M;
                cp16(smaddr(sA + row*BKP + c*8),
                     A_ + (long)(ok ? gr : 0)*lda + k0 + c*8, ok);
            }
        }
        #pragma unroll
        for (int t = 0; t < (BN*4 + THREADS - 1)/THREADS; t++) {
            const int idx = tid + t*THREADS;
            if (idx < BN*4) {
                const int row = idx >> 2, c = idx & 3;
                const int gn = n0 + row;
                const bool ok = gn < N;
                cp16(smaddr(sB + row*BKP + c*8),
                     B_ + (long)(ok ? gn : 0)*ldb + k0 + c*8, ok);
            }
        }
    };

    load_tile(0, 0);
    CP_COMMIT();

    for (int kt = 0; kt < nk; kt++) {
        if (kt + 1 < nk) load_tile((kt+1)&1, kt+1);
        CP_COMMIT();
        CP_WAIT1();
        __syncthreads();

        const int st = kt & 1;
        const h16* sA = dsm + st*STAGE;
        const h16* sB = sA + AS;

        #pragma unroll
        for (int ks = 0; ks < 2; ks++) {
            const int kcb = ks*16 + laneKof;
            uint32_t bf[N_T][2];
            #pragma unroll
            for (int p = 0; p < N_T/2; p++) {
                uint32_t r0, r1, r2, r3;
                LDSM4(r0, r1, r2, r3,
                      smaddr(sB + (wn*WN + p*16 + laneRow)*BKP + kcb));
                bf[2*p][0]=r0; bf[2*p+1][0]=r1; bf[2*p][1]=r2; bf[2*p+1][1]=r3;
            }
            #pragma unroll
            for (int i = 0; i < M_T; i++) {
                uint32_t a[4];
                LDSM4(a[0], a[1], a[2], a[3],
                      smaddr(sA + (wm*WM + i*16 + laneRow)*BKP + kcb));
                #pragma unroll
                for (int j = 0; j < N_T; j++)
                    MMA_F16(acc[i][j], a, bf[j]);
            }
        }
        __syncthreads();
    }

    // ---- epilogue ----
    #pragma unroll
    for (int i = 0; i < M_T; i++) {
        #pragma unroll
        for (int j = 0; j < N_T; j++) {
            #pragma unroll
            for (int h2 = 0; h2 < 2; h2++) {
                const int m = m0 + wm*WM + i*16 + (lane >> 2) + h2*8;
                const int n = n0 + wn*WN + j*8  + (lane & 3)*2;
                if (m >= M || n >= N) continue;
                const float v0 = acc[i][j][h2*2 + 0];
                const float v1 = acc[i][j][h2*2 + 1];
                if (EPI == 1) {
                    const long o = (long)m*ldd + n;
                    float2 r = *reinterpret_cast<const float2*>(res + o);
                    float2 w = make_float2(v0 + bias[n] + r.x, v1 + bias[n+1] + r.y);
                    *reinterpret_cast<float2*>(Df + o) = w;
                } else if (EPI == 2) {
                    const float g0 = v0 + bias[n],   g1 = v1 + bias[n+1];
                    const float e0 = 0.5f*g0*(1.0f + erff(g0*0.70710678118654752f));
                    const float e1 = 0.5f*g1*(1.0f + erff(g1*0.70710678118654752f));
                    const long o = (long)m*ldd + n;
                    *reinterpret_cast<__half2*>(D1 + o) =
                        __half2(__float2half(e0), __float2half(e1));
                } else if (EPI == 3) {
                    if (n < 1024) {
                        const long o = (long)m*1024 + n;
                        *reinterpret_cast<__half2*>(D1 + o) =
                            __half2(__float2half(v0), __float2half(v1));
                    } else if (n < 2048) {
                        const long o = (long)m*1024 + (n - 1024);
                        *reinterpret_cast<__half2*>(D2 + o) =
                            __half2(__float2half(v0), __float2half(v1));
                    } else {
                        const int b_ = m / SEQ, s_ = m % SEQ;
                        const int c0 = n - 2048;
                        const long o0 = (((long)(b_*NHEADS + (c0 >> 6)))*HDIM + (c0 & 63))*SEQP + s_;
                        const long o1 = (((long)(b_*NHEADS + ((c0+1) >> 6)))*HDIM + ((c0+1) & 63))*SEQP + s_;
                        D3[o0] = __float2half(v0);
                        D3[o1] = __float2half(v1);
                    }
                }
            }
        }
    }
}

// ---------------- fused flash attention (pure fp16) ------------------------
__global__ void __launch_bounds__(256)
flash_kernel(const h16* __restrict__ q_, const h16* __restrict__ k_,
             const h16* __restrict__ vT_,
             const float* __restrict__ mask,
             h16* __restrict__ ao)
{
    extern __shared__ h16 sm[];
    h16* sQ  = sm;
    h16* sKV = sm + 128*KVP;
    const int SSTG = 2*64*KVP;

    const int tid = threadIdx.x, lane = tid & 31, wq = tid >> 5;
    const int laneRow = (lane & 7) + ((lane >> 3) & 1) * 8;
    const int laneKof = (lane >> 4) * 8;
    const int qt = blockIdx.x;
    const int z  = blockIdx.y;
    const int b  = z >> 4, h = z & 15;
    const int q0 = qt*128;

    #pragma unroll
    for (int t = 0; t < 4; t++) {
        const int idx = tid + t*256;
        const int r = idx >> 3, c = idx & 7;
        long grow = (long)b*SEQ + q0 + r;
        if (grow > MTOT-1) grow = MTOT-1;
        cp16(smaddr(sQ + r*KVP + c*8), q_ + grow*1024 + h*64 + c*8, true);
    }
    auto load_kv = [&](int st, int ci){
        const int s0 = ci*SN;
        h16* K = sKV + st*SSTG;
        h16* V = K + 64*KVP;
        {
            const int idx = tid;               // 512 rows*8 chunks / 256 thr = 2
            #pragma unroll
            for (int t = 0; t < 2; t++) {
                const int id2 = idx + t*256;
                const int r = id2 >> 3, c = id2 & 7;
                long grow = (long)b*SEQ + s0 + r;
                if (grow > MTOT-1) grow = MTOT-1;
                cp16(smaddr(K + r*KVP + c*8), k_ + grow*1024 + h*64 + c*8, true);
                const long vo = ((long)z*HDIM + r)*SEQP + s0 + c*8;
                cp16(smaddr(V + r*KVP + c*8), vT_ + vo, true);
            }
        }
    };
    load_kv(0, 0);
    CP_COMMIT();

    uint32_t qf[4][4];
    float Oacc[8][4];
    float m_run[2] = {-1e30f, -1e30f}, l_run[2] = {0.f, 0.f};
    #pragma unroll
    for (int j = 0; j < 8; j++)
        #pragma unroll
        for (int c = 0; c < 4; c++) Oacc[j][c] = 0.f;

    for (int ci = 0; ci < NCH; ci++) {
        if (ci + 1 < NCH) load_kv((ci+1)&1, ci+1);
        CP_COMMIT();
        CP_WAIT1();
        __syncthreads();

        if (ci == 0) {
            #pragma unroll
            for (int kk = 0; kk < 4; kk++) {
                const int kcb = kk*16 + laneKof;
                LDSM4(qf[kk][0], qf[kk][1], qf[kk][2], qf[kk][3],
                      smaddr(sQ + (wq*16 + laneRow)*KVP + kcb));
            }
        }

        const int st = ci & 1;
        const h16* K = sKV + st*SSTG;
        const h16* V = K + 64*KVP;

        // ---- S = Q K^T ----
        float S[8][4];
        #pragma unroll
        for (int j = 0; j < 8; j++)
            #pragma unroll
            for (int c = 0; c < 4; c++) S[j][c] = 0.f;
        #pragma unroll
        for (int kk = 0; kk < 4; kk++) {
            const int kcb = kk*16 + laneKof;
            #pragma unroll
            for (int jp = 0; jp < 4; jp++) {
                uint32_t h0,h1,h2,h3;
                LDSM4(h0, h1, h2, h3, smaddr(K + (jp*16 + laneRow)*KVP + kcb));
                uint32_t kb0[2] = {h0, h2}, kb1[2] = {h1, h3};
                MMA_F16(S[2*jp],   qf[kk], kb0);
                MMA_F16(S[2*jp+1], qf[kk], kb1);
            }
        }

        const int s_lane = ci*SN + (lane & 3)*2;
        float mx[2] = {m_run[0], m_run[1]};
        #pragma unroll
        for (int j = 0; j < 8; j++) {
            #pragma unroll
            for (int c = 0; c < 4; c++) {
                const int s  = s_lane + j*8 + (c & 1);
                const int ch = c >> 1;
                float v = S[j][c]*SCALE;
                if (s >= SEQ) v = -1e30f;
                else if (qt == 8) {
                    const int q = q0 + wq*16 + (lane >> 2) + ch*8;
                    if (q < SEQ && s < NPATCH) {
                        const float mv = mask[((long)b*NQ + (q - NPATCH))*NPATCH + s];
                        if (!(mv > 0.5f)) v = NEG_BIG;
                    }
                }
                S[j][c] = v;
                mx[ch] = fmaxf(mx[ch], v);
            }
        }
        #pragma unroll
        for (int ch = 0; ch < 2; ch++) {
            mx[ch] = fmaxf(mx[ch], __shfl_xor_sync(0xffffffffu, mx[ch], 1));
            mx[ch] = fmaxf(mx[ch], __shfl_xor_sync(0xffffffffu, mx[ch], 2));
        }
        float alpha[2], sum[2] = {0.f, 0.f};
        #pragma unroll
        for (int ch = 0; ch < 2; ch++) alpha[ch] = __expf(m_run[ch] - mx[ch]);
        m_run[0] = mx[0]; m_run[1] = mx[1];

        #pragma unroll
        for (int j = 0; j < 8; j++) {
            #pragma unroll
            for (int c = 0; c < 4; c++) {
                const float p = __expf(S[j][c] - mx[c >> 1]);
                S[j][c] = p;
                sum[c >> 1] += p;
            }
        }
        #pragma unroll
        for (int ch = 0; ch < 2; ch++) {
            sum[ch] += __shfl_xor_sync(0xffffffffu, sum[ch], 1);
            sum[ch] += __shfl_xor_sync(0xffffffffu, sum[ch], 2);
            l_run[ch] = l_run[ch]*alpha[ch] + sum[ch];
        }
        #pragma unroll
        for (int j = 0; j < 8; j++) {
            #pragma unroll
            for (int c = 0; c < 4; c++) Oacc[j][c] *= alpha[c >> 1];
        }

        // ---- O += P V ----
        #pragma unroll
        for (int kk = 0; kk < 4; kk++) {
            uint32_t pa[4];
            #pragma unroll
            for (int half = 0; half < 2; half++) {
                const int jt = 2*kk + half;
                pa[0 + 2*half] = pack_h2(__float2half(S[jt][0]), __float2half(S[jt][1]));
                pa[1 + 2*half] = pack_h2(__float2half(S[jt][2]), __float2half(S[jt][3]));
            }
            const int kcb = kk*16 + laneKof;
            #pragma unroll
            for (int dp = 0; dp < 4; dp++) {
                uint32_t h0,h1,h2,h3;
                LDSM4(h0, h1, h2, h3, smaddr(V + (dp*16 + laneRow)*KVP + kcb));
                uint32_t vb0[2] = {h0, h2}, vb1[2] = {h1, h3};
                MMA_F16(Oacc[2*dp],   pa, vb0);
                MMA_F16(Oacc[2*dp+1], pa, vb1);
            }
        }
        __syncthreads();
    }

    #pragma unroll
    for (int ch = 0; ch < 2; ch++) {
        const int q = q0 + wq*16 + (lane >> 2) + ch*8;
        if (q >= SEQ) continue;
        const float inv = 1.0f / l_run[ch];
        const long rowo = ((long)b*SEQ + q)*EMBED + h*64;
        #pragma unroll
        for (int jd = 0; jd < 8; jd++) {
            const int d = jd*8 + (lane & 3)*2;
            *reinterpret_cast<__half2*>(ao + rowo + d) =
                __half2(__float2half(Oacc[jd][ch*2 + 0]*inv),
                        __float2half(Oacc[jd][ch*2 + 1]*inv));
        }
    }
}

// ---------------- launch ----------------
extern "C" void kernel_launch(void* const* d_in, const int* in_sizes, int n_in,
                              void* d_out, int out_size)
{
    (void)in_sizes; (void)n_in; (void)out_size;
    const float* x      = (const float*)d_in[0];
    const float* mask   = (const float*)d_in[1];
    const float* qkv_w  = (const float*)d_in[2];
    const float* proj_w = (const float*)d_in[3];
    const float* proj_b = (const float*)d_in[4];
    const float* ln1_g  = (const float*)d_in[5];
    const float* ln1_b  = (const float*)d_in[6];
    const float* ln2_g  = (const float*)d_in[7];
    const float* ln2_b  = (const float*)d_in[8];
    const float* fc1_w  = (const float*)d_in[9];
    const float* fc1_b  = (const float*)d_in[10];
    const float* fc2_w  = (const float*)d_in[11];
    const float* fc2_b  = (const float*)d_in[12];
    float* out = (float*)d_out;

    h16 *xn, *q, *k, *vT, *ao, *h1;
    h16 *wqkv, *wprj, *wfc1, *wfc2;
    float *xmid;
    cudaGetSymbolAddress((void**)&xn, g_xn);
    cudaGetSymbolAddress((void**)&q, g_q);
    cudaGetSymbolAddress((void**)&k, g_k);
    cudaGetSymbolAddress((void**)&vT, g_vT);
    cudaGetSymbolAddress((void**)&ao, g_ao);
    cudaGetSymbolAddress((void**)&h1, g_h1);
    cudaGetSymbolAddress((void**)&wqkv, g_wqkv);
    cudaGetSymbolAddress((void**)&wprj, g_wprj);
    cudaGetSymbolAddress((void**)&wfc1, g_wfc1);
    cudaGetSymbolAddress((void**)&wfc2, g_wfc2);
    cudaGetSymbolAddress((void**)&xmid, g_xmid);

    const int SMEM_G = smem_bytes(128, 128);   // 40960 B
    cudaFuncSetAttribute(tcgemm<128,128,2,4,1>, cudaFuncAttributeMaxDynamicSharedMemorySize, SMEM_G);
    cudaFuncSetAttribute(tcgemm<128,128,2,4,2>, cudaFuncAttributeMaxDynamicSharedMemorySize, SMEM_G);
    cudaFuncSetAttribute(tcgemm<128,128,2,4,3>, cudaFuncAttributeMaxDynamicSharedMemorySize, SMEM_G);
    cudaFuncSetAttribute(flash_kernel, cudaFuncAttributeMaxDynamicSharedMemorySize, FLASH_SMEM);

    const int MB = (MTOT + 127) / 128;   // 71

    wsplitT<<<dim3(3072/32, 1024/32), dim3(32,8)>>>(qkv_w,  wqkv, 1024, 3072);
    wsplitT<<<dim3(1024/32, 1024/32), dim3(32,8)>>>(proj_w, wprj, 1024, 1024);
    wsplitT<<<dim3(4096/32, 1024/32), dim3(32,8)>>>(fc1_w,  wfc1, 1024, 4096);
    wsplitT<<<dim3(1024/32, 4096/32), dim3(32,8)>>>(fc2_w,  wfc2, 4096, 1024);

    ln_kernel<<<MTOT, 256>>>(x, ln1_g, ln1_b, xn);

    // qkv (EPI=3): q / k / vT
    tcgemm<128,128,2,4,3><<<dim3(3072/128, MB, 1), 256, SMEM_G>>>(
        xn, wqkv, nullptr, nullptr,
        nullptr, q, k, vT,
        MTOT, 3072, 1024, 1024, 1024, 0);

    flash_kernel<<<dim3(9, BATCH*NHEADS), 256, FLASH_SMEM>>>(
        q, k, vT, mask, ao);

    // x_mid = ao @ proj + b + x (EPI=1)
    tcgemm<128,128,2,4,1><<<dim3(EMBED/128, MB, 1), 256, SMEM_G>>>(
        ao, wprj, proj_b, x,
        xmid, nullptr, nullptr, nullptr,
        MTOT, EMBED, 1024, 1024, 1024, EMBED);

    ln_kernel<<<MTOT, 256>>>(xmid, ln2_g, ln2_b, xn);

    // h1 = gelu(ln2 @ fc1 + b) (EPI=2)
    tcgemm<128,128,2,4,2><<<dim3(MLPH/128, MB, 1), 256, SMEM_G>>>(
        xn, wfc1, fc1_b, nullptr,
        nullptr, h1, nullptr, nullptr,
        MTOT, MLPH, 1024, 1024, 1024, MLPH);

    // out = h1 @ fc2 + b + xmid (EPI=1)
    tcgemm<128,128,2,4,1><<<dim3(EMBED/128, MB, 1), 256, SMEM_G>>>(
        h1, wfc2, fc2_b, xmid,
        out, nullptr, nullptr, nullptr,
        MTOT, EMBED, 4096, 4096, 4096, EMBED);
}

// round 14
// speedup vs baseline: 2.3003x; 1.0132x over previous
#include <cuda_runtime.h>
#include <cuda_fp16.h>
#include <math.h>
#include <stdint.h>

using h16 = __half;

// ---------------- problem constants ----------------
#define EMBED   1024
#define NHEADS  16
#define HDIM    64
#define SCALE   0.125f
#define NQ      100
#define NPATCH  1024
#define SEQ     1124
#define SEQP    1152
#define BATCH   8
#define MTOT    (BATCH*SEQ)      // 8992
#define MLPH    4096
#define LN_EPS  1e-6f
#define NEG_BIG (-1.0e9f)

// smem bytes: 3 stages x (A BM*40 + B BN*40) elems x 2 B
constexpr int smem_bytes(int BM, int BN) {
    return 3 * (BM*40 + BN*40) * 2;
}

// flash tiles
#define SN    64
#define NCH   (SEQP/SN)
#define KVP   72
constexpr int FLASH_SMEM = (128*KVP + 2*2*64*KVP) * 2;   // Q + 2 stages (K,V)

// ---------------- scratch ----------------
__device__ h16   g_xn  [MTOT*EMBED];
__device__ h16   g_q   [(long)MTOT*EMBED];
__device__ h16   g_k   [(long)MTOT*EMBED];
__device__ h16   g_vT  [(long)BATCH*NHEADS*HDIM*SEQP];
__device__ h16   g_ao  [MTOT*EMBED];
__device__ h16   g_h1  [(long)MTOT*MLPH];
__device__ float g_xmid[(long)MTOT*EMBED];
__device__ h16   g_wqkv[(long)3072*1024];
__device__ h16   g_wprj[(long)1024*1024];
__device__ h16   g_wfc1[(long)4096*1024];
__device__ h16   g_wfc2[(long)1024*4096];

// ---------------- helpers ----------------
__device__ __forceinline__ float warpSum(float v){
    #pragma unroll
    for (int o = 16; o > 0; o >>= 1) v += __shfl_xor_sync(0xffffffffu, v, o);
    return v;
}
__device__ __forceinline__ void cp16(uint32_t s, const void* g, bool valid){
    asm volatile("cp.async.cg.shared.global [%0], [%1], 16, %2;"
                 :: "r"(s), "l"(g), "r"(valid ? 16 : 0));
}
#define CP_COMMIT() asm volatile("cp.async.commit_group;" ::: "memory")
#define CP_WAIT1()  asm volatile("cp.async.wait_group 1;" ::: "memory")
__device__ __forceinline__ uint32_t smaddr(const void* p){
    return (uint32_t)__cvta_generic_to_shared(p);
}
__device__ __forceinline__ uint32_t pack_h2(h16 a, h16 b){
    __half2 t(a, b);
    return *reinterpret_cast<uint32_t*>(&t);
}

#define MMA_F16(c, a, b) \
    asm volatile("mma.sync.aligned.m16n8k16.row.col.f32.f16.f16.f32 " \
                 "{%0,%1,%2,%3},{%4,%5,%6,%7},{%8,%9},{%0,%1,%2,%3};" \
                 : "+f"(c[0]), "+f"(c[1]), "+f"(c[2]), "+f"(c[3]) \
                 : "r"(a[0]), "r"(a[1]), "r"(a[2]), "r"(a[3]), "r"(b[0]), "r"(b[1]))

#define LDSM4(r0, r1, r2, r3, addr) \
    asm volatile("ldmatrix.sync.aligned.m8n8.x4.shared.b16 {%0,%1,%2,%3}, [%4];" \
                 : "=r"(r0), "=r"(r1), "=r"(r2), "=r"(r3) : "r"(addr))

// ---------------- weight transpose to fp16: w[K][N] -> o[N][K] -------------
__global__ void wsplitT(const float* __restrict__ w, h16* __restrict__ o,
                        int K, int N)
{
    __shared__ float sm[32][33];
    const int n0 = blockIdx.x*32, k0 = blockIdx.y*32;
    #pragma unroll
    for (int i = 0; i < 4; i++) {
        const int k = threadIdx.y + i*8;
        sm[k][threadIdx.x] = w[(long)(k0+k)*N + n0 + threadIdx.x];
    }
    __syncthreads();
    #pragma unroll
    for (int i = 0; i < 4; i++) {
        const int nl = threadIdx.y + i*8;
        o[(long)(n0+nl)*K + k0 + threadIdx.x] = __float2half(sm[threadIdx.x][nl]);
    }
}

// ---------------- LayerNorm -> fp16 ----------------
__global__ void ln_kernel(const float* __restrict__ x,
                          const float* __restrict__ gamma,
                          const float* __restrict__ beta,
                          h16* __restrict__ oh)
{
    const int row = blockIdx.x;
    const int tid = threadIdx.x;
    const float4 v = reinterpret_cast<const float4*>(x + (size_t)row*EMBED)[tid];
    float s  = v.x + v.y + v.z + v.w;
    float ss = v.x*v.x + v.y*v.y + v.z*v.z + v.w*v.w;
    s = warpSum(s); ss = warpSum(ss);
    __shared__ float sh1[8], sh2[8];
    const int w = tid >> 5, l = tid & 31;
    if (l == 0) { sh1[w] = s; sh2[w] = ss; }
    __syncthreads();
    if (w == 0) {
        float a = (l < 8) ? sh1[l] : 0.f;
        float b = (l < 8) ? sh2[l] : 0.f;
        a = warpSum(a); b = warpSum(b);
        if (l == 0) { sh1[0] = a; sh2[0] = b; }
    }
    __syncthreads();
    const float mean = sh1[0] * (1.0f/EMBED);
    const float var  = sh2[0] * (1.0f/EMBED) - mean*mean;
    const float rstd = rsqrtf(var + LN_EPS);
    const float4 g4 = reinterpret_cast<const float4*>(gamma)[tid];
    const float4 b4 = reinterpret_cast<const float4*>(beta )[tid];
    float o[4];
    o[0] = (v.x - mean)*rstd*g4.x + b4.x;
    o[1] = (v.y - mean)*rstd*g4.y + b4.y;
    o[2] = (v.z - mean)*rstd*g4.z + b4.z;
    o[3] = (v.w - mean)*rstd*g4.w + b4.w;
    const long base = (long)row*EMBED + tid*4;
    *reinterpret_cast<__half2*>(oh + base + 0) = __half2(__float2half(o[0]), __float2half(o[1]));
    *reinterpret_cast<__half2*>(oh + base + 2) = __half2(__float2half(o[2]), __float2half(o[3]));
}

// ---------------- fp16 tensor-core GEMM, 3-stage cp.async pipeline ---------
// EPI: 1 Df=acc+bias+res ; 2 D1=fp16(gelu(acc+bias)) ;
//      3 qkv: n<1024 -> D1=q; n<2048 -> D2=k; else D3=vT (transposed)
template<int BM,int BN,int WMW,int WNW,int EPI>
__global__ void __launch_bounds__(WMW*WNW*32)
tcgemm(const h16* __restrict__ A_, const h16* __restrict__ B_,
       const float* __restrict__ bias, const float* __restrict__ res,
       float* __restrict__ Df, h16* __restrict__ D1, h16* __restrict__ D2,
       h16* __restrict__ D3,
       int M, int N, int K, int lda, int ldb, int ldd)
{
    constexpr int BK  = 32;
    constexpr int BKP = 40;
    constexpr int THREADS = WMW*WNW*32;
    constexpr int WM = BM/WMW, WN = BN/WNW;
    constexpr int M_T = WM/16, N_T = WN/8;
    constexpr int AS = BM*BKP, BS = BN*BKP;
    constexpr int STAGE = AS + BS;

    extern __shared__ h16 dsm[];

    const int tid  = threadIdx.x;
    const int lane = tid & 31;
    const int wid  = tid >> 5;
    const int wn   = wid % WNW;
    const int wm   = wid / WNW;
    const int laneRow = (lane & 7) + ((lane >> 3) & 1) * 8;
    const int laneKof = (lane >> 4) * 8;

    const int m0 = blockIdx.y * BM;
    const int n0 = blockIdx.x * BN;

    float acc[M_T][N_T][4];
    #pragma unroll
    for (int i = 0; i < M_T; i++)
        #pragma unroll
        for (int j = 0; j < N_T; j++)
            #pragma unroll
            for (int c = 0; c < 4; c++) acc[i][j][c] = 0.f;

    const int nk = K / BK;

    auto load_tile = [&](int st, int kt){
        const int k0 = kt * BK;
        h16* sA = dsm + st*STAGE;
        h16* sB = sA + AS;
        #pragma unroll
        for (int t = 0; t < (BM*4 + THREADS - 1)/THREADS; t++) {
            const int idx = tid + t*THREADS;
            if (idx < BM*4) {
                const int row = idx >> 2, c = idx & 3;
                const int gr = m0 + row;
                const bool ok = gr < M;
                cp16(smaddr(sA + row*BKP + c*8),
                     A_ + (long)(ok ? gr : 0)*lda + k0 + c*8, ok);
            }
        }
        #pragma unroll
        for (int t = 0; t < (BN*4 + THREADS - 1)/THREADS; t++) {
            const int idx = tid + t*THREADS;
            if (idx < BN*4) {
                const int row = idx >> 2, c = idx & 3;
                const int gn = n0 + row;
                const bool ok = gn < N;
                cp16(smaddr(sB + row*BKP + c*8),
                     B_ + (long)(ok ? gn : 0)*ldb + k0 + c*8, ok);
            }
        }
    };

    // prologue: stages 0,1 in flight
    load_tile(0, 0); CP_COMMIT();
    if (nk > 1) { load_tile(1, 1); CP_COMMIT(); }

    int st = 0;
    for (int kt = 0; kt < nk; kt++) {
        // wait until tile kt resident (kt+1 may still be in flight)
        CP_WAIT1();
        __syncthreads();

        // prefetch kt+2 into the stage freed by kt-1 (all consumers passed sync)
        if (kt + 2 < nk) {
            int st2 = st + 2; if (st2 >= 3) st2 -= 3;
            load_tile(st2, kt + 2);
            CP_COMMIT();
        }

        const h16* sA = dsm + st*STAGE;
        const h16* sB = sA + AS;

        #pragma unroll
        for (int ks = 0; ks < 2; ks++) {
            const int kcb = ks*16 + laneKof;
            uint32_t bf[N_T][2];
            #pragma unroll
            for (int p = 0; p < N_T/2; p++) {
                uint32_t r0, r1, r2, r3;
                LDSM4(r0, r1, r2, r3,
                      smaddr(sB + (wn*WN + p*16 + laneRow)*BKP + kcb));
                bf[2*p][0]=r0; bf[2*p+1][0]=r1; bf[2*p][1]=r2; bf[2*p+1][1]=r3;
            }
            #pragma unroll
            for (int i = 0; i < M_T; i++) {
                uint32_t a[4];
                LDSM4(a[0], a[1], a[2], a[3],
                      smaddr(sA + (wm*WM + i*16 + laneRow)*BKP + kcb));
                #pragma unroll
                for (int j = 0; j < N_T; j++)
                    MMA_F16(acc[i][j], a, bf[j]);
            }
        }

        if (++st == 3) st = 0;
    }

    // ---- epilogue ----
    #pragma unroll
    for (int i = 0; i < M_T; i++) {
        #pragma unroll
        for (int j = 0; j < N_T; j++) {
            #pragma unroll
            for (int h2 = 0; h2 < 2; h2++) {
                const int m = m0 + wm*WM + i*16 + (lane >> 2) + h2*8;
                const int n = n0 + wn*WN + j*8  + (lane & 3)*2;
                if (m >= M || n >= N) continue;
                const float v0 = acc[i][j][h2*2 + 0];
                const float v1 = acc[i][j][h2*2 + 1];
                if (EPI == 1) {
                    const long o = (long)m*ldd + n;
                    float2 r = *reinterpret_cast<const float2*>(res + o);
                    float2 w = make_float2(v0 + bias[n] + r.x, v1 + bias[n+1] + r.y);
                    *reinterpret_cast<float2*>(Df + o) = w;
                } else if (EPI == 2) {
                    const float g0 = v0 + bias[n],   g1 = v1 + bias[n+1];
                    const float e0 = 0.5f*g0*(1.0f + erff(g0*0.70710678118654752f));
                    const float e1 = 0.5f*g1*(1.0f + erff(g1*0.70710678118654752f));
                    const long o = (long)m*ldd + n;
                    *reinterpret_cast<__half2*>(D1 + o) =
                        __half2(__float2half(e0), __float2half(e1));
                } else if (EPI == 3) {
                    if (n < 1024) {
                        const long o = (long)m*1024 + n;
                        *reinterpret_cast<__half2*>(D1 + o) =
                            __half2(__float2half(v0), __float2half(v1));
                    } else if (n < 2048) {
                        const long o = (long)m*1024 + (n - 1024);
                        *reinterpret_cast<__half2*>(D2 + o) =
                            __half2(__float2half(v0), __float2half(v1));
                    } else {
                        const int b_ = m / SEQ, s_ = m % SEQ;
                        const int c0 = n - 2048;
                        const long o0 = (((long)(b_*NHEADS + (c0 >> 6)))*HDIM + (c0 & 63))*SEQP + s_;
                        const long o1 = (((long)(b_*NHEADS + ((c0+1) >> 6)))*HDIM + ((c0+1) & 63))*SEQP + s_;
                        D3[o0] = __float2half(v0);
                        D3[o1] = __float2half(v1);
                    }
                }
            }
        }
    }
}

// ---------------- fused flash attention (pure fp16, unchanged) -------------
__global__ void __launch_bounds__(256)
flash_kernel(const h16* __restrict__ q_, const h16* __restrict__ k_,
             const h16* __restrict__ vT_,
             const float* __restrict__ mask,
             h16* __restrict__ ao)
{
    extern __shared__ h16 sm[];
    h16* sQ  = sm;
    h16* sKV = sm + 128*KVP;
    const int SSTG = 2*64*KVP;

    const int tid = threadIdx.x, lane = tid & 31, wq = tid >> 5;
    const int laneRow = (lane & 7) + ((lane >> 3) & 1) * 8;
    const int laneKof = (lane >> 4) * 8;
    const int qt = blockIdx.x;
    const int z  = blockIdx.y;
    const int b  = z >> 4, h = z & 15;
    const int q0 = qt*128;

    #pragma unroll
    for (int t = 0; t < 4; t++) {
        const int idx = tid + t*256;
        const int r = idx >> 3, c = idx & 7;
        long grow = (long)b*SEQ + q0 + r;
        if (grow > MTOT-1) grow = MTOT-1;
        cp16(smaddr(sQ + r*KVP + c*8), q_ + grow*1024 + h*64 + c*8, true);
    }
    auto load_kv = [&](int st, int ci){
        const int s0 = ci*SN;
        h16* K = sKV + st*SSTG;
        h16* V = K + 64*KVP;
        #pragma unroll
        for (int t = 0; t < 2; t++) {
            const int id2 = tid + t*256;
            const int r = id2 >> 3, c = id2 & 7;
            long grow = (long)b*SEQ + s0 + r;
            if (grow > MTOT-1) grow = MTOT-1;
            cp16(smaddr(K + r*KVP + c*8), k_ + grow*1024 + h*64 + c*8, true);
            const long vo = ((long)z*HDIM + r)*SEQP + s0 + c*8;
            cp16(smaddr(V + r*KVP + c*8), vT_ + vo, true);
        }
    };
    load_kv(0, 0);
    CP_COMMIT();

    uint32_t qf[4][4];
    float Oacc[8][4];
    float m_run[2] = {-1e30f, -1e30f}, l_run[2] = {0.f, 0.f};
    #pragma unroll
    for (int j = 0; j < 8; j++)
        #pragma unroll
        for (int c = 0; c < 4; c++) Oacc[j][c] = 0.f;

    for (int ci = 0; ci < NCH; ci++) {
        if (ci + 1 < NCH) load_kv((ci+1)&1, ci+1);
        CP_COMMIT();
        CP_WAIT1();
        __syncthreads();

        if (ci == 0) {
            #pragma unroll
            for (int kk = 0; kk < 4; kk++) {
                const int kcb = kk*16 + laneKof;
                LDSM4(qf[kk][0], qf[kk][1], qf[kk][2], qf[kk][3],
                      smaddr(sQ + (wq*16 + laneRow)*KVP + kcb));
            }
        }

        const int st = ci & 1;
        const h16* K = sKV + st*SSTG;
        const h16* V = K + 64*KVP;

        float S[8][4];
        #pragma unroll
        for (int j = 0; j < 8; j++)
            #pragma unroll
            for (int c = 0; c < 4; c++) S[j][c] = 0.f;
        #pragma unroll
        for (int kk = 0; kk < 4; kk++) {
            const int kcb = kk*16 + laneKof;
            #pragma unroll
            for (int jp = 0; jp < 4; jp++) {
                uint32_t h0,h1,h2,h3;
                LDSM4(h0, h1, h2, h3, smaddr(K + (jp*16 + laneRow)*KVP + kcb));
                uint32_t kb0[2] = {h0, h2}, kb1[2] = {h1, h3};
                MMA_F16(S[2*jp],   qf[kk], kb0);
                MMA_F16(S[2*jp+1], qf[kk], kb1);
            }
        }

        const int s_lane = ci*SN + (lane & 3)*2;
        float mx[2] = {m_run[0], m_run[1]};
        #pragma unroll
        for (int j = 0; j < 8; j++) {
            #pragma unroll
            for (int c = 0; c < 4; c++) {
                const int s  = s_lane + j*8 + (c & 1);
                const int ch = c >> 1;
                float v = S[j][c]*SCALE;
                if (s >= SEQ) v = -1e30f;
                else if (qt == 8) {
                    const int q = q0 + wq*16 + (lane >> 2) + ch*8;
                    if (q < SEQ && s < NPATCH) {
                        const float mv = mask[((long)b*NQ + (q - NPATCH))*NPATCH + s];
                        if (!(mv > 0.5f)) v = NEG_BIG;
                    }
                }
                S[j][c] = v;
                mx[ch] = fmaxf(mx[ch], v);
            }
        }
        #pragma unroll
        for (int ch = 0; ch < 2; ch++) {
            mx[ch] = fmaxf(mx[ch], __shfl_xor_sync(0xffffffffu, mx[ch], 1));
            mx[ch] = fmaxf(mx[ch], __shfl_xor_sync(0xffffffffu, mx[ch], 2));
        }
        float alpha[2], sum[2] = {0.f, 0.f};
        #pragma unroll
        for (int ch = 0; ch < 2; ch++) alpha[ch] = __expf(m_run[ch] - mx[ch]);
        m_run[0] = mx[0]; m_run[1] = mx[1];

        #pragma unroll
        for (int j = 0; j < 8; j++) {
            #pragma unroll
            for (int c = 0; c < 4; c++) {
                const float p = __expf(S[j][c] - mx[c >> 1]);
                S[j][c] = p;
                sum[c >> 1] += p;
            }
        }
        #pragma unroll
        for (int ch = 0; ch < 2; ch++) {
            sum[ch] += __shfl_xor_sync(0xffffffffu, sum[ch], 1);
            sum[ch] += __shfl_xor_sync(0xffffffffu, sum[ch], 2);
            l_run[ch] = l_run[ch]*alpha[ch] + sum[ch];
        }
        #pragma unroll
        for (int j = 0; j < 8; j++) {
            #pragma unroll
            for (int c = 0; c < 4; c++) Oacc[j][c] *= alpha[c >> 1];
        }

        #pragma unroll
        for (int kk = 0; kk < 4; kk++) {
            uint32_t pa[4];
            #pragma unroll
            for (int half = 0; half < 2; half++) {
                const int jt = 2*kk + half;
                pa[0 + 2*half] = pack_h2(__float2half(S[jt][0]), __float2half(S[jt][1]));
                pa[1 + 2*half] = pack_h2(__float2half(S[jt][2]), __float2half(S[jt][3]));
            }
            const int kcb = kk*16 + laneKof;
            #pragma unroll
            for (int dp = 0; dp < 4; dp++) {
                uint32_t h0,h1,h2,h3;
                LDSM4(h0, h1, h2, h3, smaddr(V + (dp*16 + laneRow)*KVP + kcb));
                uint32_t vb0[2] = {h0, h2}, vb1[2] = {h1, h3};
                MMA_F16(Oacc[2*dp],   pa, vb0);
                MMA_F16(Oacc[2*dp+1], pa, vb1);
            }
        }
        __syncthreads();
    }

    #pragma unroll
    for (int ch = 0; ch < 2; ch++) {
        const int q = q0 + wq*16 + (lane >> 2) + ch*8;
        if (q >= SEQ) continue;
        const float inv = 1.0f / l_run[ch];
        const long rowo = ((long)b*SEQ + q)*EMBED + h*64;
        #pragma unroll
        for (int jd = 0; jd < 8; jd++) {
            const int d = jd*8 + (lane & 3)*2;
            *reinterpret_cast<__half2*>(ao + rowo + d) =
                __half2(__float2half(Oacc[jd][ch*2 + 0]*inv),
                        __float2half(Oacc[jd][ch*2 + 1]*inv));
        }
    }
}

// ---------------- launch ----------------
extern "C" void kernel_launch(void* const* d_in, const int* in_sizes, int n_in,
                              void* d_out, int out_size)
{
    (void)in_sizes; (void)n_in; (void)out_size;
    const float* x      = (const float*)d_in[0];
    const float* mask   = (const float*)d_in[1];
    const float* qkv_w  = (const float*)d_in[2];
    const float* proj_w = (const float*)d_in[3];
    const float* proj_b = (const float*)d_in[4];
    const float* ln1_g  = (const float*)d_in[5];
    const float* ln1_b  = (const float*)d_in[6];
    const float* ln2_g  = (const float*)d_in[7];
    const float* ln2_b  = (const float*)d_in[8];
    const float* fc1_w  = (const float*)d_in[9];
    const float* fc1_b  = (const float*)d_in[10];
    const float* fc2_w  = (const float*)d_in[11];
    const float* fc2_b  = (const float*)d_in[12];
    float* out = (float*)d_out;

    h16 *xn, *q, *k, *vT, *ao, *h1;
    h16 *wqkv, *wprj, *wfc1, *wfc2;
    float *xmid;
    cudaGetSymbolAddress((void**)&xn, g_xn);
    cudaGetSymbolAddress((void**)&q, g_q);
    cudaGetSymbolAddress((void**)&k, g_k);
    cudaGetSymbolAddress((void**)&vT, g_vT);
    cudaGetSymbolAddress((void**)&ao, g_ao);
    cudaGetSymbolAddress((void**)&h1, g_h1);
    cudaGetSymbolAddress((void**)&wqkv, g_wqkv);
    cudaGetSymbolAddress((void**)&wprj, g_wprj);
    cudaGetSymbolAddress((void**)&wfc1, g_wfc1);
    cudaGetSymbolAddress((void**)&wfc2, g_wfc2);
    cudaGetSymbolAddress((void**)&xmid, g_xmid);

    const int SMEM_G = smem_bytes(128, 128);   // 61440 B
    cudaFuncSetAttribute(tcgemm<128,128,2,4,1>, cudaFuncAttributeMaxDynamicSharedMemorySize, SMEM_G);
    cudaFuncSetAttribute(tcgemm<128,128,2,4,2>, cudaFuncAttributeMaxDynamicSharedMemorySize, SMEM_G);
    cudaFuncSetAttribute(tcgemm<128,128,2,4,3>, cudaFuncAttributeMaxDynamicSharedMemorySize, SMEM_G);
    cudaFuncSetAttribute(flash_kernel, cudaFuncAttributeMaxDynamicSharedMemorySize, FLASH_SMEM);

    const int MB = (MTOT + 127) / 128;   // 71

    wsplitT<<<dim3(3072/32, 1024/32), dim3(32,8)>>>(qkv_w,  wqkv, 1024, 3072);
    wsplitT<<<dim3(1024/32, 1024/32), dim3(32,8)>>>(proj_w, wprj, 1024, 1024);
    wsplitT<<<dim3(4096/32, 1024/32), dim3(32,8)>>>(fc1_w,  wfc1, 1024, 4096);
    wsplitT<<<dim3(1024/32, 4096/32), dim3(32,8)>>>(fc2_w,  wfc2, 4096, 1024);

    ln_kernel<<<MTOT, 256>>>(x, ln1_g, ln1_b, xn);

    // qkv (EPI=3): q / k / vT
    tcgemm<128,128,2,4,3><<<dim3(3072/128, MB, 1), 256, SMEM_G>>>(
        xn, wqkv, nullptr, nullptr,
        nullptr, q, k, vT,
        MTOT, 3072, 1024, 1024, 1024, 0);

    flash_kernel<<<dim3(9, BATCH*NHEADS), 256, FLASH_SMEM>>>(
        q, k, vT, mask, ao);

    // x_mid = ao @ proj + b + x (EPI=1)
    tcgemm<128,128,2,4,1><<<dim3(EMBED/128, MB, 1), 256, SMEM_G>>>(
        ao, wprj, proj_b, x,
        xmid, nullptr, nullptr, nullptr,
        MTOT, EMBED, 1024, 1024, 1024, EMBED);

    ln_kernel<<<MTOT, 256>>>(xmid, ln2_g, ln2_b, xn);

    // h1 = gelu(ln2 @ fc1 + b) (EPI=2)
    tcgemm<128,128,2,4,2><<<dim3(MLPH/128, MB, 1), 256, SMEM_G>>>(
        xn, wfc1, fc1_b, nullptr,
        nullptr, h1, nullptr, nullptr,
        MTOT, MLPH, 1024, 1024, 1024, MLPH);

    // out = h1 @ fc2 + b + xmid (EPI=1)
    tcgemm<128,128,2,4,1><<<dim3(EMBED/128, MB, 1), 256, SMEM_G>>>(
        h1, wfc2, fc2_b, xmid,
        out, nullptr, nullptr, nullptr,
        MTOT, EMBED, 4096, 4096, 4096, EMBED);
}

// round 15
// speedup vs baseline: 2.5887x; 1.1254x over previous
#include <cuda_runtime.h>
#include <cuda_fp16.h>
#include <math.h>
#include <stdint.h>

using h16 = __half;

// ---------------- problem constants ----------------
#define EMBED   1024
#define NHEADS  16
#define HDIM    64
#define SCALE   0.125f
#define NQ      100
#define NPATCH  1024
#define SEQ     1124
#define SEQP    1152
#define BATCH   8
#define MTOT    (BATCH*SEQ)      // 8992
#define MLPH    4096
#define LN_EPS  1e-6f
#define NEG_BIG (-1.0e9f)

// GEMM tiles: BK=64, BKP=72 (144B rows, 16B aligned, conflict-free)
#define GBK   64
#define GBKP  72
// smem bytes: 3 stages x (A BM*GBKP + B BN*GBKP) elems x 2 B
constexpr int smem_bytes(int BM, int BN) {
    return 3 * (BM*GBKP + BN*GBKP) * 2;
}

// flash tiles
#define SN    64
#define NCH   (SEQP/SN)
#define KVP   72
constexpr int FLASH_SMEM = (128*KVP + 2*2*64*KVP) * 2;   // Q + 2 stages (K,V)

// ---------------- scratch ----------------
__device__ h16   g_xn  [MTOT*EMBED];
__device__ h16   g_q   [(long)MTOT*EMBED];
__device__ h16   g_k   [(long)MTOT*EMBED];
__device__ h16   g_vT  [(long)BATCH*NHEADS*HDIM*SEQP];
__device__ h16   g_ao  [MTOT*EMBED];
__device__ h16   g_h1  [(long)MTOT*MLPH];
__device__ float g_xmid[(long)MTOT*EMBED];
__device__ h16   g_wqkv[(long)3072*1024];
__device__ h16   g_wprj[(long)1024*1024];
__device__ h16   g_wfc1[(long)4096*1024];
__device__ h16   g_wfc2[(long)1024*4096];

// ---------------- helpers ----------------
__device__ __forceinline__ float warpSum(float v){
    #pragma unroll
    for (int o = 16; o > 0; o >>= 1) v += __shfl_xor_sync(0xffffffffu, v, o);
    return v;
}
__device__ __forceinline__ void cp16(uint32_t s, const void* g, bool valid){
    asm volatile("cp.async.cg.shared.global [%0], [%1], 16, %2;"
                 :: "r"(s), "l"(g), "r"(valid ? 16 : 0));
}
#define CP_COMMIT() asm volatile("cp.async.commit_group;" ::: "memory")
#define CP_WAIT1()  asm volatile("cp.async.wait_group 1;" ::: "memory")
__device__ __forceinline__ uint32_t smaddr(const void* p){
    return (uint32_t)__cvta_generic_to_shared(p);
}
__device__ __forceinline__ uint32_t pack_h2(h16 a, h16 b){
    __half2 t(a, b);
    return *reinterpret_cast<uint32_t*>(&t);
}

#define MMA_F16(c, a, b) \
    asm volatile("mma.sync.aligned.m16n8k16.row.col.f32.f16.f16.f32 " \
                 "{%0,%1,%2,%3},{%4,%5,%6,%7},{%8,%9},{%0,%1,%2,%3};" \
                 : "+f"(c[0]), "+f"(c[1]), "+f"(c[2]), "+f"(c[3]) \
                 : "r"(a[0]), "r"(a[1]), "r"(a[2]), "r"(a[3]), "r"(b[0]), "r"(b[1]))

#define LDSM4(r0, r1, r2, r3, addr) \
    asm volatile("ldmatrix.sync.aligned.m8n8.x4.shared.b16 {%0,%1,%2,%3}, [%4];" \
                 : "=r"(r0), "=r"(r1), "=r"(r2), "=r"(r3) : "r"(addr))

// ---------------- fused weight transpose (all 4 weights, one launch) -------
// tiles: qkv 96x32=3072 | proj 32x32=1024 | fc1 128x32=4096 | fc2 32x128=4096
__global__ void wsplit_all(const float* __restrict__ w0, h16* __restrict__ o0,
                           const float* __restrict__ w1, h16* __restrict__ o1,
                           const float* __restrict__ w2, h16* __restrict__ o2,
                           const float* __restrict__ w3, h16* __restrict__ o3)
{
    int t = blockIdx.x;
    const float* w; h16* o; int K, N, n0, k0;
    if (t < 3072)      { w = w0; o = o0; K = 1024; N = 3072;
                         n0 = (t % 96)*32;  k0 = (t / 96)*32; }
    else if (t < 4096) { t -= 3072; w = w1; o = o1; K = 1024; N = 1024;
                         n0 = (t % 32)*32;  k0 = (t / 32)*32; }
    else if (t < 8192) { t -= 4096; w = w2; o = o2; K = 1024; N = 4096;
                         n0 = (t % 128)*32; k0 = (t / 128)*32; }
    else               { t -= 8192; w = w3; o = o3; K = 4096; N = 1024;
                         n0 = (t % 32)*32;  k0 = (t / 32)*32; }

    __shared__ float sm[32][33];
    #pragma unroll
    for (int i = 0; i < 4; i++) {
        const int k = threadIdx.y + i*8;
        sm[k][threadIdx.x] = w[(long)(k0+k)*N + n0 + threadIdx.x];
    }
    __syncthreads();
    #pragma unroll
    for (int i = 0; i < 4; i++) {
        const int nl = threadIdx.y + i*8;
        o[(long)(n0+nl)*K + k0 + threadIdx.x] = __float2half(sm[threadIdx.x][nl]);
    }
}

// ---------------- LayerNorm -> fp16 ----------------
__global__ void ln_kernel(const float* __restrict__ x,
                          const float* __restrict__ gamma,
                          const float* __restrict__ beta,
                          h16* __restrict__ oh)
{
    const int row = blockIdx.x;
    const int tid = threadIdx.x;
    const float4 v = reinterpret_cast<const float4*>(x + (size_t)row*EMBED)[tid];
    float s  = v.x + v.y + v.z + v.w;
    float ss = v.x*v.x + v.y*v.y + v.z*v.z + v.w*v.w;
    s = warpSum(s); ss = warpSum(ss);
    __shared__ float sh1[8], sh2[8];
    const int w = tid >> 5, l = tid & 31;
    if (l == 0) { sh1[w] = s; sh2[w] = ss; }
    __syncthreads();
    if (w == 0) {
        float a = (l < 8) ? sh1[l] : 0.f;
        float b = (l < 8) ? sh2[l] : 0.f;
        a = warpSum(a); b = warpSum(b);
        if (l == 0) { sh1[0] = a; sh2[0] = b; }
    }
    __syncthreads();
    const float mean = sh1[0] * (1.0f/EMBED);
    const float var  = sh2[0] * (1.0f/EMBED) - mean*mean;
    const float rstd = rsqrtf(var + LN_EPS);
    const float4 g4 = reinterpret_cast<const float4*>(gamma)[tid];
    const float4 b4 = reinterpret_cast<const float4*>(beta )[tid];
    float o[4];
    o[0] = (v.x - mean)*rstd*g4.x + b4.x;
    o[1] = (v.y - mean)*rstd*g4.y + b4.y;
    o[2] = (v.z - mean)*rstd*g4.z + b4.z;
    o[3] = (v.w - mean)*rstd*g4.w + b4.w;
    const long base = (long)row*EMBED + tid*4;
    *reinterpret_cast<__half2*>(oh + base + 0) = __half2(__float2half(o[0]), __float2half(o[1]));
    *reinterpret_cast<__half2*>(oh + base + 2) = __half2(__float2half(o[2]), __float2half(o[3]));
}

// ---------------- fp16 tensor-core GEMM, BK=64, 3-stage pipeline -----------
// EPI: 1 Df=acc+bias+res ; 2 D1=fp16(gelu(acc+bias)) ;
//      3 qkv: n<1024 -> D1=q; n<2048 -> D2=k; else D3=vT (transposed)
template<int BM,int BN,int WMW,int WNW,int EPI>
__global__ void __launch_bounds__(WMW*WNW*32)
tcgemm(const h16* __restrict__ A_, const h16* __restrict__ B_,
       const float* __restrict__ bias, const float* __restrict__ res,
       float* __restrict__ Df, h16* __restrict__ D1, h16* __restrict__ D2,
       h16* __restrict__ D3,
       int M, int N, int K, int lda, int ldb, int ldd)
{
    constexpr int BK  = GBK;
    constexpr int BKP = GBKP;
    constexpr int THREADS = WMW*WNW*32;
    constexpr int WM = BM/WMW, WN = BN/WNW;
    constexpr int M_T = WM/16, N_T = WN/8;
    constexpr int AS = BM*BKP, BS = BN*BKP;
    constexpr int STAGE = AS + BS;

    extern __shared__ h16 dsm[];

    const int tid  = threadIdx.x;
    const int lane = tid & 31;
    const int wid  = tid >> 5;
    const int wn   = wid % WNW;
    const int wm   = wid / WNW;
    const int laneRow = (lane & 7) + ((lane >> 3) & 1) * 8;
    const int laneKof = (lane >> 4) * 8;

    const int m0 = blockIdx.y * BM;
    const int n0 = blockIdx.x * BN;

    float acc[M_T][N_T][4];
    #pragma unroll
    for (int i = 0; i < M_T; i++)
        #pragma unroll
        for (int j = 0; j < N_T; j++)
            #pragma unroll
            for (int c = 0; c < 4; c++) acc[i][j][c] = 0.f;

    const int nk = K / BK;

    auto load_tile = [&](int st, int kt){
        const int k0 = kt * BK;
        h16* sA = dsm + st*STAGE;
        h16* sB = sA + AS;
        #pragma unroll
        for (int t = 0; t < (BM*8 + THREADS - 1)/THREADS; t++) {
            const int idx = tid + t*THREADS;
            if (idx < BM*8) {
                const int row = idx >> 3, c = idx & 7;
                const int gr = m0 + row;
                const bool ok = gr < M;
                cp16(smaddr(sA + row*BKP + c*8),
                     A_ + (long)(ok ? gr : 0)*lda + k0 + c*8, ok);
            }
        }
        #pragma unroll
        for (int t = 0; t < (BN*8 + THREADS - 1)/THREADS; t++) {
            const int idx = tid + t*THREADS;
            if (idx < BN*8) {
                const int row = idx >> 3, c = idx & 7;
                const int gn = n0 + row;
                const bool ok = gn < N;
                cp16(smaddr(sB + row*BKP + c*8),
                     B_ + (long)(ok ? gn : 0)*ldb + k0 + c*8, ok);
            }
        }
    };

    // prologue: stages 0,1 in flight
    load_tile(0, 0); CP_COMMIT();
    if (nk > 1) { load_tile(1, 1); CP_COMMIT(); }

    int st = 0;
    for (int kt = 0; kt < nk; kt++) {
        CP_WAIT1();
        __syncthreads();

        if (kt + 2 < nk) {
            int st2 = st + 2; if (st2 >= 3) st2 -= 3;
            load_tile(st2, kt + 2);
            CP_COMMIT();
        }

        const h16* sA = dsm + st*STAGE;
        const h16* sB = sA + AS;

        #pragma unroll
        for (int ks = 0; ks < 4; ks++) {
            const int kcb = ks*16 + laneKof;
            uint32_t bf[N_T][2];
            #pragma unroll
            for (int p = 0; p < N_T/2; p++) {
                uint32_t r0, r1, r2, r3;
                LDSM4(r0, r1, r2, r3,
                      smaddr(sB + (wn*WN + p*16 + laneRow)*BKP + kcb));
                bf[2*p][0]=r0; bf[2*p+1][0]=r1; bf[2*p][1]=r2; bf[2*p+1][1]=r3;
            }
            #pragma unroll
            for (int i = 0; i < M_T; i++) {
                uint32_t a[4];
                LDSM4(a[0], a[1], a[2], a[3],
                      smaddr(sA + (wm*WM + i*16 + laneRow)*BKP + kcb));
                #pragma unroll
                for (int j = 0; j < N_T; j++)
                    MMA_F16(acc[i][j], a, bf[j]);
            }
        }

        if (++st == 3) st = 0;
    }

    // ---- epilogue ----
    #pragma unroll
    for (int i = 0; i < M_T; i++) {
        #pragma unroll
        for (int j = 0; j < N_T; j++) {
            #pragma unroll
            for (int h2 = 0; h2 < 2; h2++) {
                const int m = m0 + wm*WM + i*16 + (lane >> 2) + h2*8;
                const int n = n0 + wn*WN + j*8  + (lane & 3)*2;
                if (m >= M || n >= N) continue;
                const float v0 = acc[i][j][h2*2 + 0];
                const float v1 = acc[i][j][h2*2 + 1];
                if (EPI == 1) {
                    const long o = (long)m*ldd + n;
                    float2 r = *reinterpret_cast<const float2*>(res + o);
                    float2 w = make_float2(v0 + bias[n] + r.x, v1 + bias[n+1] + r.y);
                    *reinterpret_cast<float2*>(Df + o) = w;
                } else if (EPI == 2) {
                    const float g0 = v0 + bias[n],   g1 = v1 + bias[n+1];
                    const float e0 = 0.5f*g0*(1.0f + erff(g0*0.70710678118654752f));
                    const float e1 = 0.5f*g1*(1.0f + erff(g1*0.70710678118654752f));
                    const long o = (long)m*ldd + n;
                    *reinterpret_cast<__half2*>(D1 + o) =
                        __half2(__float2half(e0), __float2half(e1));
                } else if (EPI == 3) {
                    if (n < 1024) {
                        const long o = (long)m*1024 + n;
                        *reinterpret_cast<__half2*>(D1 + o) =
                            __half2(__float2half(v0), __float2half(v1));
                    } else if (n < 2048) {
                        const long o = (long)m*1024 + (n - 1024);
                        *reinterpret_cast<__half2*>(D2 + o) =
                            __half2(__float2half(v0), __float2half(v1));
                    } else {
                        const int b_ = m / SEQ, s_ = m % SEQ;
                        const int c0 = n - 2048;
                        const long o0 = (((long)(b_*NHEADS + (c0 >> 6)))*HDIM + (c0 & 63))*SEQP + s_;
                        const long o1 = (((long)(b_*NHEADS + ((c0+1) >> 6)))*HDIM + ((c0+1) & 63))*SEQP + s_;
                        D3[o0] = __float2half(v0);
                        D3[o1] = __float2half(v1);
                    }
                }
            }
        }
    }
}

// ---------------- fused flash attention (pure fp16, unchanged) -------------
__global__ void __launch_bounds__(256)
flash_kernel(const h16* __restrict__ q_, const h16* __restrict__ k_,
             const h16* __restrict__ vT_,
             const float* __restrict__ mask,
             h16* __restrict__ ao)
{
    extern __shared__ h16 sm[];
    h16* sQ  = sm;
    h16* sKV = sm + 128*KVP;
    const int SSTG = 2*64*KVP;

    const int tid = threadIdx.x, lane = tid & 31, wq = tid >> 5;
    const int laneRow = (lane & 7) + ((lane >> 3) & 1) * 8;
    const int laneKof = (lane >> 4) * 8;
    const int qt = blockIdx.x;
    const int z  = blockIdx.y;
    const int b  = z >> 4, h = z & 15;
    const int q0 = qt*128;

    #pragma unroll
    for (int t = 0; t < 4; t++) {
        const int idx = tid + t*256;
        const int r = idx >> 3, c = idx & 7;
        long grow = (long)b*SEQ + q0 + r;
        if (grow > MTOT-1) grow = MTOT-1;
        cp16(smaddr(sQ + r*KVP + c*8), q_ + grow*1024 + h*64 + c*8, true);
    }
    auto load_kv = [&](int st, int ci){
        const int s0 = ci*SN;
        h16* K = sKV + st*SSTG;
        h16* V = K + 64*KVP;
        #pragma unroll
        for (int t = 0; t < 2; t++) {
            const int id2 = tid + t*256;
            const int r = id2 >> 3, c = id2 & 7;
            long grow = (long)b*SEQ + s0 + r;
            if (grow > MTOT-1) grow = MTOT-1;
            cp16(smaddr(K + r*KVP + c*8), k_ + grow*1024 + h*64 + c*8, true);
            const long vo = ((long)z*HDIM + r)*SEQP + s0 + c*8;
            cp16(smaddr(V + r*KVP + c*8), vT_ + vo, true);
        }
    };
    load_kv(0, 0);
    CP_COMMIT();

    uint32_t qf[4][4];
    float Oacc[8][4];
    float m_run[2] = {-1e30f, -1e30f}, l_run[2] = {0.f, 0.f};
    #pragma unroll
    for (int j = 0; j < 8; j++)
        #pragma unroll
        for (int c = 0; c < 4; c++) Oacc[j][c] = 0.f;

    for (int ci = 0; ci < NCH; ci++) {
        if (ci + 1 < NCH) load_kv((ci+1)&1, ci+1);
        CP_COMMIT();
        CP_WAIT1();
        __syncthreads();

        if (ci == 0) {
            #pragma unroll
            for (int kk = 0; kk < 4; kk++) {
                const int kcb = kk*16 + laneKof;
                LDSM4(qf[kk][0], qf[kk][1], qf[kk][2], qf[kk][3],
                      smaddr(sQ + (wq*16 + laneRow)*KVP + kcb));
            }
        }

        const int st = ci & 1;
        const h16* K = sKV + st*SSTG;
        const h16* V = K + 64*KVP;

        float S[8][4];
        #pragma unroll
        for (int j = 0; j < 8; j++)
            #pragma unroll
            for (int c = 0; c < 4; c++) S[j][c] = 0.f;
        #pragma unroll
        for (int kk = 0; kk < 4; kk++) {
            const int kcb = kk*16 + laneKof;
            #pragma unroll
            for (int jp = 0; jp < 4; jp++) {
                uint32_t h0,h1,h2,h3;
                LDSM4(h0, h1, h2, h3, smaddr(K + (jp*16 + laneRow)*KVP + kcb));
                uint32_t kb0[2] = {h0, h2}, kb1[2] = {h1, h3};
                MMA_F16(S[2*jp],   qf[kk], kb0);
                MMA_F16(S[2*jp+1], qf[kk], kb1);
            }
        }

        const int s_lane = ci*SN + (lane & 3)*2;
        float mx[2] = {m_run[0], m_run[1]};
        #pragma unroll
        for (int j = 0; j < 8; j++) {
            #pragma unroll
            for (int c = 0; c < 4; c++) {
                const int s  = s_lane + j*8 + (c & 1);
                const int ch = c >> 1;
                float v = S[j][c]*SCALE;
                if (s >= SEQ) v = -1e30f;
                else if (qt == 8) {
                    const int q = q0 + wq*16 + (lane >> 2) + ch*8;
                    if (q < SEQ && s < NPATCH) {
                        const float mv = mask[((long)b*NQ + (q - NPATCH))*NPATCH + s];
                        if (!(mv > 0.5f)) v = NEG_BIG;
                    }
                }
                S[j][c] = v;
                mx[ch] = fmaxf(mx[ch], v);
            }
        }
        #pragma unroll
        for (int ch = 0; ch < 2; ch++) {
            mx[ch] = fmaxf(mx[ch], __shfl_xor_sync(0xffffffffu, mx[ch], 1));
            mx[ch] = fmaxf(mx[ch], __shfl_xor_sync(0xffffffffu, mx[ch], 2));
        }
        float alpha[2], sum[2] = {0.f, 0.f};
        #pragma unroll
        for (int ch = 0; ch < 2; ch++) alpha[ch] = __expf(m_run[ch] - mx[ch]);
        m_run[0] = mx[0]; m_run[1] = mx[1];

        #pragma unroll
        for (int j = 0; j < 8; j++) {
            #pragma unroll
            for (int c = 0; c < 4; c++) {
                const float p = __expf(S[j][c] - mx[c >> 1]);
                S[j][c] = p;
                sum[c >> 1] += p;
            }
        }
        #pragma unroll
        for (int ch = 0; ch < 2; ch++) {
            sum[ch] += __shfl_xor_sync(0xffffffffu, sum[ch], 1);
            sum[ch] += __shfl_xor_sync(0xffffffffu, sum[ch], 2);
            l_run[ch] = l_run[ch]*alpha[ch] + sum[ch];
        }
        #pragma unroll
        for (int j = 0; j < 8; j++) {
            #pragma unroll
            for (int c = 0; c < 4; c++) Oacc[j][c] *= alpha[c >> 1];
        }

        #pragma unroll
        for (int kk = 0; kk < 4; kk++) {
            uint32_t pa[4];
            #pragma unroll
            for (int half = 0; half < 2; half++) {
                const int jt = 2*kk + half;
                pa[0 + 2*half] = pack_h2(__float2half(S[jt][0]), __float2half(S[jt][1]));
                pa[1 + 2*half] = pack_h2(__float2half(S[jt][2]), __float2half(S[jt][3]));
            }
            const int kcb = kk*16 + laneKof;
            #pragma unroll
            for (int dp = 0; dp < 4; dp++) {
                uint32_t h0,h1,h2,h3;
                LDSM4(h0, h1, h2, h3, smaddr(V + (dp*16 + laneRow)*KVP + kcb));
                uint32_t vb0[2] = {h0, h2}, vb1[2] = {h1, h3};
                MMA_F16(Oacc[2*dp],   pa, vb0);
                MMA_F16(Oacc[2*dp+1], pa, vb1);
            }
        }
        __syncthreads();
    }

    #pragma unroll
    for (int ch = 0; ch < 2; ch++) {
        const int q = q0 + wq*16 + (lane >> 2) + ch*8;
        if (q >= SEQ) continue;
        const float inv = 1.0f / l_run[ch];
        const long rowo = ((long)b*SEQ + q)*EMBED + h*64;
        #pragma unroll
        for (int jd = 0; jd < 8; jd++) {
            const int d = jd*8 + (lane & 3)*2;
            *reinterpret_cast<__half2*>(ao + rowo + d) =
                __half2(__float2half(Oacc[jd][ch*2 + 0]*inv),
                        __float2half(Oacc[jd][ch*2 + 1]*inv));
        }
    }
}

// ---------------- launch ----------------
extern "C" void kernel_launch(void* const* d_in, const int* in_sizes, int n_in,
                              void* d_out, int out_size)
{
    (void)in_sizes; (void)n_in; (void)out_size;
    const float* x      = (const float*)d_in[0];
    const float* mask   = (const float*)d_in[1];
    const float* qkv_w  = (const float*)d_in[2];
    const float* proj_w = (const float*)d_in[3];
    const float* proj_b = (const float*)d_in[4];
    const float* ln1_g  = (const float*)d_in[5];
    const float* ln1_b  = (const float*)d_in[6];
    const float* ln2_g  = (const float*)d_in[7];
    const float* ln2_b  = (const float*)d_in[8];
    const float* fc1_w  = (const float*)d_in[9];
    const float* fc1_b  = (const float*)d_in[10];
    const float* fc2_w  = (const float*)d_in[11];
    const float* fc2_b  = (const float*)d_in[12];
    float* out = (float*)d_out;

    h16 *xn, *q, *k, *vT, *ao, *h1;
    h16 *wqkv, *wprj, *wfc1, *wfc2;
    float *xmid;
    cudaGetSymbolAddress((void**)&xn, g_xn);
    cudaGetSymbolAddress((void**)&q, g_q);
    cudaGetSymbolAddress((void**)&k, g_k);
    cudaGetSymbolAddress((void**)&vT, g_vT);
    cudaGetSymbolAddress((void**)&ao, g_ao);
    cudaGetSymbolAddress((void**)&h1, g_h1);
    cudaGetSymbolAddress((void**)&wqkv, g_wqkv);
    cudaGetSymbolAddress((void**)&wprj, g_wprj);
    cudaGetSymbolAddress((void**)&wfc1, g_wfc1);
    cudaGetSymbolAddress((void**)&wfc2, g_wfc2);
    cudaGetSymbolAddress((void**)&xmid, g_xmid);

    const int SMEM_G = smem_bytes(128, 128);   // 110592 B
    cudaFuncSetAttribute(tcgemm<128,128,2,4,1>, cudaFuncAttributeMaxDynamicSharedMemorySize, SMEM_G);
    cudaFuncSetAttribute(tcgemm<128,128,2,4,2>, cudaFuncAttributeMaxDynamicSharedMemorySize, SMEM_G);
    cudaFuncSetAttribute(tcgemm<128,128,2,4,3>, cudaFuncAttributeMaxDynamicSharedMemorySize, SMEM_G);
    cudaFuncSetAttribute(flash_kernel, cudaFuncAttributeMaxDynamicSharedMemorySize, FLASH_SMEM);

    const int MB = (MTOT + 127) / 128;   // 71

    // all four weight transposes in one launch
    wsplit_all<<<12288, dim3(32,8)>>>(qkv_w, wqkv, proj_w, wprj, fc1_w, wfc1, fc2_w, wfc2);

    ln_kernel<<<MTOT, 256>>>(x, ln1_g, ln1_b, xn);

    // qkv (EPI=3): q / k / vT
    tcgemm<128,128,2,4,3><<<dim3(3072/128, MB, 1), 256, SMEM_G>>>(
        xn, wqkv, nullptr, nullptr,
        nullptr, q, k, vT,
        MTOT, 3072, 1024, 1024, 1024, 0);

    flash_kernel<<<dim3(9, BATCH*NHEADS), 256, FLASH_SMEM>>>(
        q, k, vT, mask, ao);

    // x_mid = ao @ proj + b + x (EPI=1)
    tcgemm<128,128,2,4,1><<<dim3(EMBED/128, MB, 1), 256, SMEM_G>>>(
        ao, wprj, proj_b, x,
        xmid, nullptr, nullptr, nullptr,
        MTOT, EMBED, 1024, 1024, 1024, EMBED);

    ln_kernel<<<MTOT, 256>>>(xmid, ln2_g, ln2_b, xn);

    // h1 = gelu(ln2 @ fc1 + b) (EPI=2)
    tcgemm<128,128,2,4,2><<<dim3(MLPH/128, MB, 1), 256, SMEM_G>>>(
        xn, wfc1, fc1_b, nullptr,
        nullptr, h1, nullptr, nullptr,
        MTOT, MLPH, 1024, 1024, 1024, MLPH);

    // out = h1 @ fc2 + b + xmid (EPI=1)
    tcgemm<128,128,2,4,1><<<dim3(EMBED/128, MB, 1), 256, SMEM_G>>>(
        h1, wfc2, fc2_b, xmid,
        out, nullptr, nullptr, nullptr,
        MTOT, EMBED, 4096, 4096, 4096, EMBED);
}

// round 16
// speedup vs baseline: 2.6314x; 1.0165x over previous
#include <cuda_runtime.h>
#include <cuda_fp16.h>
#include <math.h>
#include <stdint.h>

using h16 = __half;

// ---------------- problem constants ----------------
#define EMBED   1024
#define NHEADS  16
#define HDIM    64
#define SCALE   0.125f
#define LOG2E   1.4426950408889634f
#define NQ      100
#define NPATCH  1024
#define SEQ     1124
#define SEQP    1152
#define BATCH   8
#define MTOT    (BATCH*SEQ)      // 8992
#define MLPH    4096
#define LN_EPS  1e-6f
#define NEG_BIG (-1.0e9f)

// GEMM tiles: BK=64, BKP=72
#define GBK   64
#define GBKP  72
constexpr int smem_bytes(int BM, int BN) {
    return 3 * (BM*GBKP + BN*GBKP) * 2;
}

// flash tiles
#define SN    64
#define NCH   (SEQP/SN)
#define KVP   72
constexpr int FLASH_SMEM = (128*KVP + 2*2*64*KVP) * 2;   // Q + 2 stages (K,V)

// ---------------- scratch ----------------
__device__ h16   g_xn  [MTOT*EMBED];
__device__ h16   g_q   [(long)MTOT*EMBED];
__device__ h16   g_k   [(long)MTOT*EMBED];
__device__ h16   g_v   [(long)MTOT*EMBED];
__device__ h16   g_ao  [MTOT*EMBED];
__device__ h16   g_h1  [(long)MTOT*MLPH];
__device__ float g_xmid[(long)MTOT*EMBED];
__device__ h16   g_wqkv[(long)3072*1024];
__device__ h16   g_wprj[(long)1024*1024];
__device__ h16   g_wfc1[(long)4096*1024];
__device__ h16   g_wfc2[(long)1024*4096];

// ---------------- helpers ----------------
__device__ __forceinline__ float warpSum(float v){
    #pragma unroll
    for (int o = 16; o > 0; o >>= 1) v += __shfl_xor_sync(0xffffffffu, v, o);
    return v;
}
__device__ __forceinline__ void cp16(uint32_t s, const void* g, bool valid){
    asm volatile("cp.async.cg.shared.global [%0], [%1], 16, %2;"
                 :: "r"(s), "l"(g), "r"(valid ? 16 : 0));
}
#define CP_COMMIT() asm volatile("cp.async.commit_group;" ::: "memory")
#define CP_WAIT0()  asm volatile("cp.async.wait_group 0;" ::: "memory")
#define CP_WAIT1()  asm volatile("cp.async.wait_group 1;" ::: "memory")
__device__ __forceinline__ uint32_t smaddr(const void* p){
    return (uint32_t)__cvta_generic_to_shared(p);
}
__device__ __forceinline__ uint32_t pack_h2(h16 a, h16 b){
    __half2 t(a, b);
    return *reinterpret_cast<uint32_t*>(&t);
}

#define MMA_F16(c, a, b) \
    asm volatile("mma.sync.aligned.m16n8k16.row.col.f32.f16.f16.f32 " \
                 "{%0,%1,%2,%3},{%4,%5,%6,%7},{%8,%9},{%0,%1,%2,%3};" \
                 : "+f"(c[0]), "+f"(c[1]), "+f"(c[2]), "+f"(c[3]) \
                 : "r"(a[0]), "r"(a[1]), "r"(a[2]), "r"(a[3]), "r"(b[0]), "r"(b[1]))

#define LDSM4(r0, r1, r2, r3, addr) \
    asm volatile("ldmatrix.sync.aligned.m8n8.x4.shared.b16 {%0,%1,%2,%3}, [%4];" \
                 : "=r"(r0), "=r"(r1), "=r"(r2), "=r"(r3) : "r"(addr))

#define LDSM4T(r0, r1, r2, r3, addr) \
    asm volatile("ldmatrix.sync.aligned.m8n8.x4.trans.shared.b16 {%0,%1,%2,%3}, [%4];" \
                 : "=r"(r0), "=r"(r1), "=r"(r2), "=r"(r3) : "r"(addr))

// ---------------- fused weight transpose (all 4 weights, one launch) -------
__global__ void wsplit_all(const float* __restrict__ w0, h16* __restrict__ o0,
                           const float* __restrict__ w1, h16* __restrict__ o1,
                           const float* __restrict__ w2, h16* __restrict__ o2,
                           const float* __restrict__ w3, h16* __restrict__ o3)
{
    int t = blockIdx.x;
    const float* w; h16* o; int K, N, n0, k0;
    if (t < 3072)      { w = w0; o = o0; K = 1024; N = 3072;
                         n0 = (t % 96)*32;  k0 = (t / 96)*32; }
    else if (t < 4096) { t -= 3072; w = w1; o = o1; K = 1024; N = 1024;
                         n0 = (t % 32)*32;  k0 = (t / 32)*32; }
    else if (t < 8192) { t -= 4096; w = w2; o = o2; K = 1024; N = 4096;
                         n0 = (t % 128)*32; k0 = (t / 128)*32; }
    else               { t -= 8192; w = w3; o = o3; K = 4096; N = 1024;
                         n0 = (t % 32)*32;  k0 = (t / 32)*32; }

    __shared__ float sm[32][33];
    #pragma unroll
    for (int i = 0; i < 4; i++) {
        const int k = threadIdx.y + i*8;
        sm[k][threadIdx.x] = w[(long)(k0+k)*N + n0 + threadIdx.x];
    }
    __syncthreads();
    #pragma unroll
    for (int i = 0; i < 4; i++) {
        const int nl = threadIdx.y + i*8;
        o[(long)(n0+nl)*K + k0 + threadIdx.x] = __float2half(sm[threadIdx.x][nl]);
    }
}

// ---------------- LayerNorm -> fp16 ----------------
__global__ void ln_kernel(const float* __restrict__ x,
                          const float* __restrict__ gamma,
                          const float* __restrict__ beta,
                          h16* __restrict__ oh)
{
    const int row = blockIdx.x;
    const int tid = threadIdx.x;
    const float4 v = reinterpret_cast<const float4*>(x + (size_t)row*EMBED)[tid];
    float s  = v.x + v.y + v.z + v.w;
    float ss = v.x*v.x + v.y*v.y + v.z*v.z + v.w*v.w;
    s = warpSum(s); ss = warpSum(ss);
    __shared__ float sh1[8], sh2[8];
    const int w = tid >> 5, l = tid & 31;
    if (l == 0) { sh1[w] = s; sh2[w] = ss; }
    __syncthreads();
    if (w == 0) {
        float a = (l < 8) ? sh1[l] : 0.f;
        float b = (l < 8) ? sh2[l] : 0.f;
        a = warpSum(a); b = warpSum(b);
        if (l == 0) { sh1[0] = a; sh2[0] = b; }
    }
    __syncthreads();
    const float mean = sh1[0] * (1.0f/EMBED);
    const float var  = sh2[0] * (1.0f/EMBED) - mean*mean;
    const float rstd = rsqrtf(var + LN_EPS);
    const float4 g4 = reinterpret_cast<const float4*>(gamma)[tid];
    const float4 b4 = reinterpret_cast<const float4*>(beta )[tid];
    float o[4];
    o[0] = (v.x - mean)*rstd*g4.x + b4.x;
    o[1] = (v.y - mean)*rstd*g4.y + b4.y;
    o[2] = (v.z - mean)*rstd*g4.z + b4.z;
    o[3] = (v.w - mean)*rstd*g4.w + b4.w;
    const long base = (long)row*EMBED + tid*4;
    *reinterpret_cast<__half2*>(oh + base + 0) = __half2(__float2half(o[0]), __float2half(o[1]));
    *reinterpret_cast<__half2*>(oh + base + 2) = __half2(__float2half(o[2]), __float2half(o[3]));
}

// ---------------- fp16 tensor-core GEMM, BK=64, 3-stage pipeline -----------
// EPI: 1 Df=acc+bias+res ; 2 D1=fp16(gelu(acc+bias)) ;
//      3 qkv: n<1024 -> D1=q; n<2048 -> D2=k; else D3=v (all row-major ld 1024)
template<int BM,int BN,int WMW,int WNW,int EPI>
__global__ void __launch_bounds__(WMW*WNW*32)
tcgemm(const h16* __restrict__ A_, const h16* __restrict__ B_,
       const float* __restrict__ bias, const float* __restrict__ res,
       float* __restrict__ Df, h16* __restrict__ D1, h16* __restrict__ D2,
       h16* __restrict__ D3,
       int M, int N, int K, int lda, int ldb, int ldd)
{
    constexpr int BK  = GBK;
    constexpr int BKP = GBKP;
    constexpr int THREADS = WMW*WNW*32;
    constexpr int WM = BM/WMW, WN = BN/WNW;
    constexpr int M_T = WM/16, N_T = WN/8;
    constexpr int AS = BM*BKP, BS = BN*BKP;
    constexpr int STAGE = AS + BS;

    extern __shared__ h16 dsm[];

    const int tid  = threadIdx.x;
    const int lane = tid & 31;
    const int wid  = tid >> 5;
    const int wn   = wid % WNW;
    const int wm   = wid / WNW;
    const int laneRow = (lane & 7) + ((lane >> 3) & 1) * 8;
    const int laneKof = (lane >> 4) * 8;

    const int m0 = blockIdx.y * BM;
    const int n0 = blockIdx.x * BN;

    float acc[M_T][N_T][4];
    #pragma unroll
    for (int i = 0; i < M_T; i++)
        #pragma unroll
        for (int j = 0; j < N_T; j++)
            #pragma unroll
            for (int c = 0; c < 4; c++) acc[i][j][c] = 0.f;

    const int nk = K / BK;

    auto load_tile = [&](int st, int kt){
        const int k0 = kt * BK;
        h16* sA = dsm + st*STAGE;
        h16* sB = sA + AS;
        #pragma unroll
        for (int t = 0; t < (BM*8 + THREADS - 1)/THREADS; t++) {
            const int idx = tid + t*THREADS;
            if (idx < BM*8) {
                const int row = idx >> 3, c = idx & 7;
                const int gr = m0 + row;
                const bool ok = gr < M;
                cp16(smaddr(sA + row*BKP + c*8),
                     A_ + (long)(ok ? gr : 0)*lda + k0 + c*8, ok);
            }
        }
        #pragma unroll
        for (int t = 0; t < (BN*8 + THREADS - 1)/THREADS; t++) {
            const int idx = tid + t*THREADS;
            if (idx < BN*8) {
                const int row = idx >> 3, c = idx & 7;
                const int gn = n0 + row;
                const bool ok = gn < N;
                cp16(smaddr(sB + row*BKP + c*8),
                     B_ + (long)(ok ? gn : 0)*ldb + k0 + c*8, ok);
            }
        }
    };

    load_tile(0, 0); CP_COMMIT();
    if (nk > 1) { load_tile(1, 1); CP_COMMIT(); }

    int st = 0;
    for (int kt = 0; kt < nk; kt++) {
        CP_WAIT1();
        __syncthreads();

        if (kt + 2 < nk) {
            int st2 = st + 2; if (st2 >= 3) st2 -= 3;
            load_tile(st2, kt + 2);
            CP_COMMIT();
        }

        const h16* sA = dsm + st*STAGE;
        const h16* sB = sA + AS;

        #pragma unroll
        for (int ks = 0; ks < 4; ks++) {
            const int kcb = ks*16 + laneKof;
            uint32_t bf[N_T][2];
            #pragma unroll
            for (int p = 0; p < N_T/2; p++) {
                uint32_t r0, r1, r2, r3;
                LDSM4(r0, r1, r2, r3,
                      smaddr(sB + (wn*WN + p*16 + laneRow)*BKP + kcb));
                bf[2*p][0]=r0; bf[2*p+1][0]=r1; bf[2*p][1]=r2; bf[2*p+1][1]=r3;
            }
            #pragma unroll
            for (int i = 0; i < M_T; i++) {
                uint32_t a[4];
                LDSM4(a[0], a[1], a[2], a[3],
                      smaddr(sA + (wm*WM + i*16 + laneRow)*BKP + kcb));
                #pragma unroll
                for (int j = 0; j < N_T; j++)
                    MMA_F16(acc[i][j], a, bf[j]);
            }
        }

        if (++st == 3) st = 0;
    }

    // ---- epilogue ----
    #pragma unroll
    for (int i = 0; i < M_T; i++) {
        #pragma unroll
        for (int j = 0; j < N_T; j++) {
            #pragma unroll
            for (int h2 = 0; h2 < 2; h2++) {
                const int m = m0 + wm*WM + i*16 + (lane >> 2) + h2*8;
                const int n = n0 + wn*WN + j*8  + (lane & 3)*2;
                if (m >= M || n >= N) continue;
                const float v0 = acc[i][j][h2*2 + 0];
                const float v1 = acc[i][j][h2*2 + 1];
                if (EPI == 1) {
                    const long o = (long)m*ldd + n;
                    float2 r = *reinterpret_cast<const float2*>(res + o);
                    float2 w = make_float2(v0 + bias[n] + r.x, v1 + bias[n+1] + r.y);
                    *reinterpret_cast<float2*>(Df + o) = w;
                } else if (EPI == 2) {
                    const float g0 = v0 + bias[n],   g1 = v1 + bias[n+1];
                    const float e0 = 0.5f*g0*(1.0f + erff(g0*0.70710678118654752f));
                    const float e1 = 0.5f*g1*(1.0f + erff(g1*0.70710678118654752f));
                    const long o = (long)m*ldd + n;
                    *reinterpret_cast<__half2*>(D1 + o) =
                        __half2(__float2half(e0), __float2half(e1));
                } else if (EPI == 3) {
                    h16* dst = (n < 1024) ? D1 : (n < 2048 ? D2 : D3);
                    const int nn = n & 1023;
                    *reinterpret_cast<__half2*>(dst + (long)m*1024 + nn) =
                        __half2(__float2half(v0), __float2half(v1));
                }
            }
        }
    }
}

// ---------------- fused flash attention (fp16, V row-major + LDSM.trans) ---
__global__ void __launch_bounds__(256)
flash_kernel(const h16* __restrict__ q_, const h16* __restrict__ k_,
             const h16* __restrict__ v_,
             const float* __restrict__ mask,
             h16* __restrict__ ao)
{
    extern __shared__ h16 sm[];
    h16* sQ  = sm;
    h16* sKV = sm + 128*KVP;
    const int SSTG = 2*64*KVP;

    const int tid = threadIdx.x, lane = tid & 31, wq = tid >> 5;
    const int laneRow = (lane & 7) + ((lane >> 3) & 1) * 8;
    const int laneKof = (lane >> 4) * 8;
    const int qt = blockIdx.x;
    const int z  = blockIdx.y;
    const int b  = z >> 4, h = z & 15;
    const int q0 = qt*128;
    const float kscale = SCALE * LOG2E;   // exp2 domain

    #pragma unroll
    for (int t = 0; t < 4; t++) {
        const int idx = tid + t*256;
        const int r = idx >> 3, c = idx & 7;
        long grow = (long)b*SEQ + q0 + r;
        if (grow > MTOT-1) grow = MTOT-1;
        cp16(smaddr(sQ + r*KVP + c*8), q_ + grow*1024 + h*64 + c*8, true);
    }
    auto load_kv = [&](int st, int ci){
        const int s0 = ci*SN;
        h16* K = sKV + st*SSTG;
        h16* V = K + 64*KVP;
        #pragma unroll
        for (int t = 0; t < 2; t++) {
            const int id2 = tid + t*256;
            const int r = id2 >> 3, c = id2 & 7;
            long grow = (long)b*SEQ + s0 + r;
            if (grow > MTOT-1) grow = MTOT-1;
            const long go = grow*1024 + h*64 + c*8;
            cp16(smaddr(K + r*KVP + c*8), k_ + go, true);
            cp16(smaddr(V + r*KVP + c*8), v_ + go, true);   // [s][d] rows
        }
    };
    load_kv(0, 0);
    CP_COMMIT();

    uint32_t qf[4][4];
    float Oacc[8][4];
    float m_run[2] = {-1e30f, -1e30f}, l_run[2] = {0.f, 0.f};
    #pragma unroll
    for (int j = 0; j < 8; j++)
        #pragma unroll
        for (int c = 0; c < 4; c++) Oacc[j][c] = 0.f;

    for (int ci = 0; ci < NCH; ci++) {
        CP_WAIT0();
        __syncthreads();          // publish chunk ci; retire readers of ci-1

        // prefetch ci+1 into the stage freed by ci-1 (overlaps compute)
        if (ci + 1 < NCH) { load_kv((ci+1)&1, ci+1); CP_COMMIT(); }

        if (ci == 0) {
            #pragma unroll
            for (int kk = 0; kk < 4; kk++) {
                const int kcb = kk*16 + laneKof;
                LDSM4(qf[kk][0], qf[kk][1], qf[kk][2], qf[kk][3],
                      smaddr(sQ + (wq*16 + laneRow)*KVP + kcb));
            }
        }

        const int st = ci & 1;
        const h16* K = sKV + st*SSTG;
        const h16* V = K + 64*KVP;

        // ---- S = Q K^T ----
        float S[8][4];
        #pragma unroll
        for (int j = 0; j < 8; j++)
            #pragma unroll
            for (int c = 0; c < 4; c++) S[j][c] = 0.f;
        #pragma unroll
        for (int kk = 0; kk < 4; kk++) {
            const int kcb = kk*16 + laneKof;
            #pragma unroll
            for (int jp = 0; jp < 4; jp++) {
                uint32_t h0,h1,h2,h3;
                LDSM4(h0, h1, h2, h3, smaddr(K + (jp*16 + laneRow)*KVP + kcb));
                uint32_t kb0[2] = {h0, h2}, kb1[2] = {h1, h3};
                MMA_F16(S[2*jp],   qf[kk], kb0);
                MMA_F16(S[2*jp+1], qf[kk], kb1);
            }
        }

        // ---- scale (log2 domain) + bounds + mask, chunk max ----
        const int s_lane = ci*SN + (lane & 3)*2;
        float mx[2] = {m_run[0], m_run[1]};
        #pragma unroll
        for (int j = 0; j < 8; j++) {
            #pragma unroll
            for (int c = 0; c < 4; c++) {
                const int s  = s_lane + j*8 + (c & 1);
                const int ch = c >> 1;
                float v = S[j][c]*kscale;
                if (s >= SEQ) v = -1e30f;
                else if (qt == 8) {
                    const int q = q0 + wq*16 + (lane >> 2) + ch*8;
                    if (q < SEQ && s < NPATCH) {
                        const float mv = mask[((long)b*NQ + (q - NPATCH))*NPATCH + s];
                        if (!(mv > 0.5f)) v = NEG_BIG;
                    }
                }
                S[j][c] = v;
                mx[ch] = fmaxf(mx[ch], v);
            }
        }
        #pragma unroll
        for (int ch = 0; ch < 2; ch++) {
            mx[ch] = fmaxf(mx[ch], __shfl_xor_sync(0xffffffffu, mx[ch], 1));
            mx[ch] = fmaxf(mx[ch], __shfl_xor_sync(0xffffffffu, mx[ch], 2));
        }
        float alpha[2], sum[2] = {0.f, 0.f};
        #pragma unroll
        for (int ch = 0; ch < 2; ch++) alpha[ch] = exp2f(m_run[ch] - mx[ch]);
        m_run[0] = mx[0]; m_run[1] = mx[1];

        #pragma unroll
        for (int j = 0; j < 8; j++) {
            #pragma unroll
            for (int c = 0; c < 4; c++) {
                const float p = exp2f(S[j][c] - mx[c >> 1]);
                S[j][c] = p;
                sum[c >> 1] += p;
            }
        }
        #pragma unroll
        for (int ch = 0; ch < 2; ch++) {
            sum[ch] += __shfl_xor_sync(0xffffffffu, sum[ch], 1);
            sum[ch] += __shfl_xor_sync(0xffffffffu, sum[ch], 2);
            l_run[ch] = l_run[ch]*alpha[ch] + sum[ch];
        }
        #pragma unroll
        for (int j = 0; j < 8; j++) {
            #pragma unroll
            for (int c = 0; c < 4; c++) Oacc[j][c] *= alpha[c >> 1];
        }

        // ---- O += P V (LDSM.trans on [s][d] tiles) ----
        #pragma unroll
        for (int kk = 0; kk < 4; kk++) {
            uint32_t pa[4];
            #pragma unroll
            for (int half = 0; half < 2; half++) {
                const int jt = 2*kk + half;
                pa[0 + 2*half] = pack_h2(__float2half(S[jt][0]), __float2half(S[jt][1]));
                pa[1 + 2*half] = pack_h2(__float2half(S[jt][2]), __float2half(S[jt][3]));
            }
            #pragma unroll
            for (int dp = 0; dp < 4; dp++) {
                uint32_t r0,r1,r2,r3;
                LDSM4T(r0, r1, r2, r3,
                       smaddr(V + (kk*16 + laneRow)*KVP + dp*16 + laneKof));
                uint32_t vb0[2] = {r0, r1}, vb1[2] = {r2, r3};
                MMA_F16(Oacc[2*dp],   pa, vb0);
                MMA_F16(Oacc[2*dp+1], pa, vb1);
            }
        }
    }

    #pragma unroll
    for (int ch = 0; ch < 2; ch++) {
        const int q = q0 + wq*16 + (lane >> 2) + ch*8;
        if (q >= SEQ) continue;
        const float inv = 1.0f / l_run[ch];
        const long rowo = ((long)b*SEQ + q)*EMBED + h*64;
        #pragma unroll
        for (int jd = 0; jd < 8; jd++) {
            const int d = jd*8 + (lane & 3)*2;
            *reinterpret_cast<__half2*>(ao + rowo + d) =
                __half2(__float2half(Oacc[jd][ch*2 + 0]*inv),
                        __float2half(Oacc[jd][ch*2 + 1]*inv));
        }
    }
}

// ---------------- launch ----------------
extern "C" void kernel_launch(void* const* d_in, const int* in_sizes, int n_in,
                              void* d_out, int out_size)
{
    (void)in_sizes; (void)n_in; (void)out_size;
    const float* x      = (const float*)d_in[0];
    const float* mask   = (const float*)d_in[1];
    const float* qkv_w  = (const float*)d_in[2];
    const float* proj_w = (const float*)d_in[3];
    const float* proj_b = (const float*)d_in[4];
    const float* ln1_g  = (const float*)d_in[5];
    const float* ln1_b  = (const float*)d_in[6];
    const float* ln2_g  = (const float*)d_in[7];
    const float* ln2_b  = (const float*)d_in[8];
    const float* fc1_w  = (const float*)d_in[9];
    const float* fc1_b  = (const float*)d_in[10];
    const float* fc2_w  = (const float*)d_in[11];
    const float* fc2_b  = (const float*)d_in[12];
    float* out = (float*)d_out;

    h16 *xn, *q, *k, *v, *ao, *h1;
    h16 *wqkv, *wprj, *wfc1, *wfc2;
    float *xmid;
    cudaGetSymbolAddress((void**)&xn, g_xn);
    cudaGetSymbolAddress((void**)&q, g_q);
    cudaGetSymbolAddress((void**)&k, g_k);
    cudaGetSymbolAddress((void**)&v, g_v);
    cudaGetSymbolAddress((void**)&ao, g_ao);
    cudaGetSymbolAddress((void**)&h1, g_h1);
    cudaGetSymbolAddress((void**)&wqkv, g_wqkv);
    cudaGetSymbolAddress((void**)&wprj, g_wprj);
    cudaGetSymbolAddress((void**)&wfc1, g_wfc1);
    cudaGetSymbolAddress((void**)&wfc2, g_wfc2);
    cudaGetSymbolAddress((void**)&xmid, g_xmid);

    const int SMEM_G = smem_bytes(128, 128);   // 110592 B
    cudaFuncSetAttribute(tcgemm<128,128,2,4,1>, cudaFuncAttributeMaxDynamicSharedMemorySize, SMEM_G);
    cudaFuncSetAttribute(tcgemm<128,128,2,4,2>, cudaFuncAttributeMaxDynamicSharedMemorySize, SMEM_G);
    cudaFuncSetAttribute(tcgemm<128,128,2,4,3>, cudaFuncAttributeMaxDynamicSharedMemorySize, SMEM_G);
    cudaFuncSetAttribute(flash_kernel, cudaFuncAttributeMaxDynamicSharedMemorySize, FLASH_SMEM);

    const int MB = (MTOT + 127) / 128;   // 71

    wsplit_all<<<12288, dim3(32,8)>>>(qkv_w, wqkv, proj_w, wprj, fc1_w, wfc1, fc2_w, wfc2);

    ln_kernel<<<MTOT, 256>>>(x, ln1_g, ln1_b, xn);

    // qkv (EPI=3): q / k / v (all row-major, ld 1024)
    tcgemm<128,128,2,4,3><<<dim3(3072/128, MB, 1), 256, SMEM_G>>>(
        xn, wqkv, nullptr, nullptr,
        nullptr, q, k, v,
        MTOT, 3072, 1024, 1024, 1024, 0);

    flash_kernel<<<dim3(9, BATCH*NHEADS), 256, FLASH_SMEM>>>(
        q, k, v, mask, ao);

    // x_mid = ao @ proj + b + x (EPI=1)
    tcgemm<128,128,2,4,1><<<dim3(EMBED/128, MB, 1), 256, SMEM_G>>>(
        ao, wprj, proj_b, x,
        xmid, nullptr, nullptr, nullptr,
        MTOT, EMBED, 1024, 1024, 1024, EMBED);

    ln_kernel<<<MTOT, 256>>>(xmid, ln2_g, ln2_b, xn);

    // h1 = gelu(ln2 @ fc1 + b) (EPI=2)
    tcgemm<128,128,2,4,2><<<dim3(MLPH/128, MB, 1), 256, SMEM_G>>>(
        xn, wfc1, fc1_b, nullptr,
        nullptr, h1, nullptr, nullptr,
        MTOT, MLPH, 1024, 1024, 1024, MLPH);

    // out = h1 @ fc2 + b + xmid (EPI=1)
    tcgemm<128,128,2,4,1><<<dim3(EMBED/128, MB, 1), 256, SMEM_G>>>(
        h1, wfc2, fc2_b, xmid,
        out, nullptr, nullptr, nullptr,
        MTOT, EMBED, 4096, 4096, 4096, EMBED);
}

// round 17
// speedup vs baseline: 2.8728x; 1.0917x over previous
#include <cuda_runtime.h>
#include <cuda_fp16.h>
#include <math.h>
#include <stdint.h>

using h16 = __half;

// ---------------- problem constants ----------------
#define EMBED   1024
#define NHEADS  16
#define HDIM    64
#define SCALE   0.125f
#define LOG2E   1.4426950408889634f
#define NQ      100
#define NPATCH  1024
#define SEQ     1124
#define SEQP    1152
#define BATCH   8
#define MTOT    (BATCH*SEQ)      // 8992
#define MLPH    4096
#define LN_EPS  1e-6f
#define NEG_BIG (-1.0e9f)

// GEMM tiles: BK=64, BKP=72
#define GBK   64
#define GBKP  72
constexpr int smem_bytes(int BM, int BN) {
    return 3 * (BM*GBKP + BN*GBKP) * 2;
}

// flash tiles
#define SN    64
#define NCH   (SEQP/SN)      // 18
#define KVP   72
constexpr int FLASH_SMEM = (128*KVP + 2*2*64*KVP) * 2;   // Q + 2 stages (K,V)

// ---------------- scratch ----------------
__device__ h16   g_xn  [MTOT*EMBED];
__device__ h16   g_q   [(long)MTOT*EMBED];
__device__ h16   g_k   [(long)MTOT*EMBED];
__device__ h16   g_v   [(long)MTOT*EMBED];
__device__ h16   g_ao  [MTOT*EMBED];
__device__ h16   g_h1  [(long)MTOT*MLPH];
__device__ float g_xmid[(long)MTOT*EMBED];
__device__ h16   g_wqkv[(long)3072*1024];
__device__ h16   g_wprj[(long)1024*1024];
__device__ h16   g_wfc1[(long)4096*1024];
__device__ h16   g_wfc2[(long)1024*4096];

// ---------------- helpers ----------------
__device__ __forceinline__ float warpSum(float v){
    #pragma unroll
    for (int o = 16; o > 0; o >>= 1) v += __shfl_xor_sync(0xffffffffu, v, o);
    return v;
}
__device__ __forceinline__ void cp16(uint32_t s, const void* g, bool valid){
    asm volatile("cp.async.cg.shared.global [%0], [%1], 16, %2;"
                 :: "r"(s), "l"(g), "r"(valid ? 16 : 0));
}
#define CP_COMMIT() asm volatile("cp.async.commit_group;" ::: "memory")
#define CP_WAIT0()  asm volatile("cp.async.wait_group 0;" ::: "memory")
#define CP_WAIT1()  asm volatile("cp.async.wait_group 1;" ::: "memory")
__device__ __forceinline__ uint32_t smaddr(const void* p){
    return (uint32_t)__cvta_generic_to_shared(p);
}
__device__ __forceinline__ uint32_t pack_h2(h16 a, h16 b){
    __half2 t(a, b);
    return *reinterpret_cast<uint32_t*>(&t);
}

#define MMA_F16(c, a, b) \
    asm volatile("mma.sync.aligned.m16n8k16.row.col.f32.f16.f16.f32 " \
                 "{%0,%1,%2,%3},{%4,%5,%6,%7},{%8,%9},{%0,%1,%2,%3};" \
                 : "+f"(c[0]), "+f"(c[1]), "+f"(c[2]), "+f"(c[3]) \
                 : "r"(a[0]), "r"(a[1]), "r"(a[2]), "r"(a[3]), "r"(b[0]), "r"(b[1]))

#define LDSM4(r0, r1, r2, r3, addr) \
    asm volatile("ldmatrix.sync.aligned.m8n8.x4.shared.b16 {%0,%1,%2,%3}, [%4];" \
                 : "=r"(r0), "=r"(r1), "=r"(r2), "=r"(r3) : "r"(addr))

#define LDSM4T(r0, r1, r2, r3, addr) \
    asm volatile("ldmatrix.sync.aligned.m8n8.x4.trans.shared.b16 {%0,%1,%2,%3}, [%4];" \
                 : "=r"(r0), "=r"(r1), "=r"(r2), "=r"(r3) : "r"(addr))

// ---------------- fused weight transpose (all 4 weights, one launch) -------
__global__ void wsplit_all(const float* __restrict__ w0, h16* __restrict__ o0,
                           const float* __restrict__ w1, h16* __restrict__ o1,
                           const float* __restrict__ w2, h16* __restrict__ o2,
                           const float* __restrict__ w3, h16* __restrict__ o3)
{
    int t = blockIdx.x;
    const float* w; h16* o; int K, N, n0, k0;
    if (t < 3072)      { w = w0; o = o0; K = 1024; N = 3072;
                         n0 = (t % 96)*32;  k0 = (t / 96)*32; }
    else if (t < 4096) { t -= 3072; w = w1; o = o1; K = 1024; N = 1024;
                         n0 = (t % 32)*32;  k0 = (t / 32)*32; }
    else if (t < 8192) { t -= 4096; w = w2; o = o2; K = 1024; N = 4096;
                         n0 = (t % 128)*32; k0 = (t / 128)*32; }
    else               { t -= 8192; w = w3; o = o3; K = 4096; N = 1024;
                         n0 = (t % 32)*32;  k0 = (t / 32)*32; }

    __shared__ float sm[32][33];
    #pragma unroll
    for (int i = 0; i < 4; i++) {
        const int k = threadIdx.y + i*8;
        sm[k][threadIdx.x] = w[(long)(k0+k)*N + n0 + threadIdx.x];
    }
    __syncthreads();
    #pragma unroll
    for (int i = 0; i < 4; i++) {
        const int nl = threadIdx.y + i*8;
        o[(long)(n0+nl)*K + k0 + threadIdx.x] = __float2half(sm[threadIdx.x][nl]);
    }
}

// ---------------- LayerNorm -> fp16 ----------------
__global__ void ln_kernel(const float* __restrict__ x,
                          const float* __restrict__ gamma,
                          const float* __restrict__ beta,
                          h16* __restrict__ oh)
{
    const int row = blockIdx.x;
    const int tid = threadIdx.x;
    const float4 v = reinterpret_cast<const float4*>(x + (size_t)row*EMBED)[tid];
    float s  = v.x + v.y + v.z + v.w;
    float ss = v.x*v.x + v.y*v.y + v.z*v.z + v.w*v.w;
    s = warpSum(s); ss = warpSum(ss);
    __shared__ float sh1[8], sh2[8];
    const int w = tid >> 5, l = tid & 31;
    if (l == 0) { sh1[w] = s; sh2[w] = ss; }
    __syncthreads();
    if (w == 0) {
        float a = (l < 8) ? sh1[l] : 0.f;
        float b = (l < 8) ? sh2[l] : 0.f;
        a = warpSum(a); b = warpSum(b);
        if (l == 0) { sh1[0] = a; sh2[0] = b; }
    }
    __syncthreads();
    const float mean = sh1[0] * (1.0f/EMBED);
    const float var  = sh2[0] * (1.0f/EMBED) - mean*mean;
    const float rstd = rsqrtf(var + LN_EPS);
    const float4 g4 = reinterpret_cast<const float4*>(gamma)[tid];
    const float4 b4 = reinterpret_cast<const float4*>(beta )[tid];
    float o[4];
    o[0] = (v.x - mean)*rstd*g4.x + b4.x;
    o[1] = (v.y - mean)*rstd*g4.y + b4.y;
    o[2] = (v.z - mean)*rstd*g4.z + b4.z;
    o[3] = (v.w - mean)*rstd*g4.w + b4.w;
    const long base = (long)row*EMBED + tid*4;
    *reinterpret_cast<__half2*>(oh + base + 0) = __half2(__float2half(o[0]), __float2half(o[1]));
    *reinterpret_cast<__half2*>(oh + base + 2) = __half2(__float2half(o[2]), __float2half(o[3]));
}

// ---------------- fp16 tensor-core GEMM, BK=64, 3-stage pipeline -----------
template<int BM,int BN,int WMW,int WNW,int EPI>
__global__ void __launch_bounds__(WMW*WNW*32)
tcgemm(const h16* __restrict__ A_, const h16* __restrict__ B_,
       const float* __restrict__ bias, const float* __restrict__ res,
       float* __restrict__ Df, h16* __restrict__ D1, h16* __restrict__ D2,
       h16* __restrict__ D3,
       int M, int N, int K, int lda, int ldb, int ldd)
{
    constexpr int BK  = GBK;
    constexpr int BKP = GBKP;
    constexpr int THREADS = WMW*WNW*32;
    constexpr int WM = BM/WMW, WN = BN/WNW;
    constexpr int M_T = WM/16, N_T = WN/8;
    constexpr int AS = BM*BKP, BS = BN*BKP;
    constexpr int STAGE = AS + BS;

    extern __shared__ h16 dsm[];

    const int tid  = threadIdx.x;
    const int lane = tid & 31;
    const int wid  = tid >> 5;
    const int wn   = wid % WNW;
    const int wm   = wid / WNW;
    const int laneRow = (lane & 7) + ((lane >> 3) & 1) * 8;
    const int laneKof = (lane >> 4) * 8;

    const int m0 = blockIdx.y * BM;
    const int n0 = blockIdx.x * BN;

    float acc[M_T][N_T][4];
    #pragma unroll
    for (int i = 0; i < M_T; i++)
        #pragma unroll
        for (int j = 0; j < N_T; j++)
            #pragma unroll
            for (int c = 0; c < 4; c++) acc[i][j][c] = 0.f;

    const int nk = K / BK;

    auto load_tile = [&](int st, int kt){
        const int k0 = kt * BK;
        h16* sA = dsm + st*STAGE;
        h16* sB = sA + AS;
        #pragma unroll
        for (int t = 0; t < (BM*8 + THREADS - 1)/THREADS; t++) {
            const int idx = tid + t*THREADS;
            if (idx < BM*8) {
                const int row = idx >> 3, c = idx & 7;
                const int gr = m0 + row;
                const bool ok = gr < M;
                cp16(smaddr(sA + row*BKP + c*8),
                     A_ + (long)(ok ? gr : 0)*lda + k0 + c*8, ok);
            }
        }
        #pragma unroll
        for (int t = 0; t < (BN*8 + THREADS - 1)/THREADS; t++) {
            const int idx = tid + t*THREADS;
            if (idx < BN*8) {
                const int row = idx >> 3, c = idx & 7;
                const int gn = n0 + row;
                const bool ok = gn < N;
                cp16(smaddr(sB + row*BKP + c*8),
                     B_ + (long)(ok ? gn : 0)*ldb + k0 + c*8, ok);
            }
        }
    };

    load_tile(0, 0); CP_COMMIT();
    if (nk > 1) { load_tile(1, 1); CP_COMMIT(); }

    int st = 0;
    for (int kt = 0; kt < nk; kt++) {
        CP_WAIT1();
        __syncthreads();

        if (kt + 2 < nk) {
            int st2 = st + 2; if (st2 >= 3) st2 -= 3;
            load_tile(st2, kt + 2);
            CP_COMMIT();
        }

        const h16* sA = dsm + st*STAGE;
        const h16* sB = sA + AS;

        #pragma unroll
        for (int ks = 0; ks < 4; ks++) {
            const int kcb = ks*16 + laneKof;
            uint32_t bf[N_T][2];
            #pragma unroll
            for (int p = 0; p < N_T/2; p++) {
                uint32_t r0, r1, r2, r3;
                LDSM4(r0, r1, r2, r3,
                      smaddr(sB + (wn*WN + p*16 + laneRow)*BKP + kcb));
                bf[2*p][0]=r0; bf[2*p+1][0]=r1; bf[2*p][1]=r2; bf[2*p+1][1]=r3;
            }
            #pragma unroll
            for (int i = 0; i < M_T; i++) {
                uint32_t a[4];
                LDSM4(a[0], a[1], a[2], a[3],
                      smaddr(sA + (wm*WM + i*16 + laneRow)*BKP + kcb));
                #pragma unroll
                for (int j = 0; j < N_T; j++)
                    MMA_F16(acc[i][j], a, bf[j]);
            }
        }

        if (++st == 3) st = 0;
    }

    // ---- epilogue ----
    #pragma unroll
    for (int i = 0; i < M_T; i++) {
        #pragma unroll
        for (int j = 0; j < N_T; j++) {
            #pragma unroll
            for (int h2 = 0; h2 < 2; h2++) {
                const int m = m0 + wm*WM + i*16 + (lane >> 2) + h2*8;
                const int n = n0 + wn*WN + j*8  + (lane & 3)*2;
                if (m >= M || n >= N) continue;
                const float v0 = acc[i][j][h2*2 + 0];
                const float v1 = acc[i][j][h2*2 + 1];
                if (EPI == 1) {
                    const long o = (long)m*ldd + n;
                    float2 r = *reinterpret_cast<const float2*>(res + o);
                    float2 w = make_float2(v0 + bias[n] + r.x, v1 + bias[n+1] + r.y);
                    *reinterpret_cast<float2*>(Df + o) = w;
                } else if (EPI == 2) {
                    const float g0 = v0 + bias[n],   g1 = v1 + bias[n+1];
                    const float e0 = 0.5f*g0*(1.0f + erff(g0*0.70710678118654752f));
                    const float e1 = 0.5f*g1*(1.0f + erff(g1*0.70710678118654752f));
                    const long o = (long)m*ldd + n;
                    *reinterpret_cast<__half2*>(D1 + o) =
                        __half2(__float2half(e0), __float2half(e1));
                } else if (EPI == 3) {
                    h16* dst = (n < 1024) ? D1 : (n < 2048 ? D2 : D3);
                    const int nn = n & 1023;
                    *reinterpret_cast<__half2*>(dst + (long)m*1024 + nn) =
                        __half2(__float2half(v0), __float2half(v1));
                }
            }
        }
    }
}

// ---------------- fused flash attention (specialized predicate paths) ------
__global__ void __launch_bounds__(256)
flash_kernel(const h16* __restrict__ q_, const h16* __restrict__ k_,
             const h16* __restrict__ v_,
             const float* __restrict__ mask,
             h16* __restrict__ ao)
{
    extern __shared__ h16 sm[];
    h16* sQ  = sm;
    h16* sKV = sm + 128*KVP;
    const int SSTG = 2*64*KVP;

    const int tid = threadIdx.x, lane = tid & 31, wq = tid >> 5;
    const int laneRow = (lane & 7) + ((lane >> 3) & 1) * 8;
    const int laneKof = (lane >> 4) * 8;
    const int qt = blockIdx.x;
    const int z  = blockIdx.y;
    const int b  = z >> 4, h = z & 15;
    const int q0 = qt*128;
    const float kscale = SCALE * LOG2E;   // exp2 domain
    const bool is_qtile8 = (qt == 8);

    #pragma unroll
    for (int t = 0; t < 4; t++) {
        const int idx = tid + t*256;
        const int r = idx >> 3, c = idx & 7;
        long grow = (long)b*SEQ + q0 + r;
        if (grow > MTOT-1) grow = MTOT-1;
        cp16(smaddr(sQ + r*KVP + c*8), q_ + grow*1024 + h*64 + c*8, true);
    }
    auto load_kv = [&](int st, int ci){
        const int s0 = ci*SN;
        h16* K = sKV + st*SSTG;
        h16* V = K + 64*KVP;
        #pragma unroll
        for (int t = 0; t < 2; t++) {
            const int id2 = tid + t*256;
            const int r = id2 >> 3, c = id2 & 7;
            long grow = (long)b*SEQ + s0 + r;
            if (grow > MTOT-1) grow = MTOT-1;
            const long go = grow*1024 + h*64 + c*8;
            cp16(smaddr(K + r*KVP + c*8), k_ + go, true);
            cp16(smaddr(V + r*KVP + c*8), v_ + go, true);
        }
    };
    load_kv(0, 0);
    CP_COMMIT();

    uint32_t qf[4][4];
    float Oacc[8][4];
    float m_run[2] = {-1e30f, -1e30f}, l_run[2] = {0.f, 0.f};
    #pragma unroll
    for (int j = 0; j < 8; j++)
        #pragma unroll
        for (int c = 0; c < 4; c++) Oacc[j][c] = 0.f;

    for (int ci = 0; ci < NCH; ci++) {
        CP_WAIT0();
        __syncthreads();

        if (ci + 1 < NCH) { load_kv((ci+1)&1, ci+1); CP_COMMIT(); }

        if (ci == 0) {
            #pragma unroll
            for (int kk = 0; kk < 4; kk++) {
                const int kcb = kk*16 + laneKof;
                LDSM4(qf[kk][0], qf[kk][1], qf[kk][2], qf[kk][3],
                      smaddr(sQ + (wq*16 + laneRow)*KVP + kcb));
            }
        }

        const int st = ci & 1;
        const h16* K = sKV + st*SSTG;
        const h16* V = K + 64*KVP;

        // ---- S = Q K^T ----
        float S[8][4];
        #pragma unroll
        for (int j = 0; j < 8; j++)
            #pragma unroll
            for (int c = 0; c < 4; c++) S[j][c] = 0.f;
        #pragma unroll
        for (int kk = 0; kk < 4; kk++) {
            const int kcb = kk*16 + laneKof;
            #pragma unroll
            for (int jp = 0; jp < 4; jp++) {
                uint32_t h0,h1,h2,h3;
                LDSM4(h0, h1, h2, h3, smaddr(K + (jp*16 + laneRow)*KVP + kcb));
                uint32_t kb0[2] = {h0, h2}, kb1[2] = {h1, h3};
                MMA_F16(S[2*jp],   qf[kk], kb0);
                MMA_F16(S[2*jp+1], qf[kk], kb1);
            }
        }

        // ---- scale + (specialized) mask/bounds + chunk max ----
        float mx[2] = {m_run[0], m_run[1]};
        if (ci == NCH-1) {
            // bounds path: s in [1088,1152), SEQ=1124 cutoff; no mask possible
            const int s_lane = ci*SN + (lane & 3)*2;
            #pragma unroll
            for (int j = 0; j < 8; j++) {
                #pragma unroll
                for (int c = 0; c < 4; c++) {
                    const int s  = s_lane + j*8 + (c & 1);
                    float v = (s < SEQ) ? S[j][c]*kscale : -1e30f;
                    S[j][c] = v;
                    mx[c >> 1] = fmaxf(mx[c >> 1], v);
                }
            }
        } else if (is_qtile8 && ci <= 15) {
            // mask path: s < 1024 always in these chunks
            const int s_lane = ci*SN + (lane & 3)*2;
            #pragma unroll
            for (int j = 0; j < 8; j++) {
                #pragma unroll
                for (int c = 0; c < 4; c++) {
                    const int s  = s_lane + j*8 + (c & 1);
                    const int ch = c >> 1;
                    const int q = q0 + wq*16 + (lane >> 2) + ch*8;
                    float v = S[j][c]*kscale;
                    if (q < SEQ) {
                        const float mv = mask[((long)b*NQ + (q - NPATCH))*NPATCH + s];
                        if (!(mv > 0.5f)) v = NEG_BIG;
                    }
                    S[j][c] = v;
                    mx[ch] = fmaxf(mx[ch], v);
                }
            }
        } else {
            // pure path: no bounds, no mask
            #pragma unroll
            for (int j = 0; j < 8; j++) {
                #pragma unroll
                for (int c = 0; c < 4; c++) {
                    const float v = S[j][c]*kscale;
                    S[j][c] = v;
                    mx[c >> 1] = fmaxf(mx[c >> 1], v);
                }
            }
        }
        #pragma unroll
        for (int ch = 0; ch < 2; ch++) {
            mx[ch] = fmaxf(mx[ch], __shfl_xor_sync(0xffffffffu, mx[ch], 1));
            mx[ch] = fmaxf(mx[ch], __shfl_xor_sync(0xffffffffu, mx[ch], 2));
        }
        float alpha[2], sum[2] = {0.f, 0.f};
        #pragma unroll
        for (int ch = 0; ch < 2; ch++) alpha[ch] = exp2f(m_run[ch] - mx[ch]);
        m_run[0] = mx[0]; m_run[1] = mx[1];

        #pragma unroll
        for (int j = 0; j < 8; j++) {
            #pragma unroll
            for (int c = 0; c < 4; c++) {
                const float p = exp2f(S[j][c] - mx[c >> 1]);
                S[j][c] = p;
                sum[c >> 1] += p;
            }
        }
        #pragma unroll
        for (int ch = 0; ch < 2; ch++) {
            sum[ch] += __shfl_xor_sync(0xffffffffu, sum[ch], 1);
            sum[ch] += __shfl_xor_sync(0xffffffffu, sum[ch], 2);
            l_run[ch] = l_run[ch]*alpha[ch] + sum[ch];
        }
        // rescale only if some lane's max moved (x*1.0 is a bit-exact no-op)
        if (__any_sync(0xffffffffu, (alpha[0] != 1.0f) | (alpha[1] != 1.0f))) {
            #pragma unroll
            for (int j = 0; j < 8; j++) {
                #pragma unroll
                for (int c = 0; c < 4; c++) Oacc[j][c] *= alpha[c >> 1];
            }
        }

        // ---- O += P V ----
        #pragma unroll
        for (int kk = 0; kk < 4; kk++) {
            uint32_t pa[4];
            #pragma unroll
            for (int half = 0; half < 2; half++) {
                const int jt = 2*kk + half;
                pa[0 + 2*half] = pack_h2(__float2half(S[jt][0]), __float2half(S[jt][1]));
                pa[1 + 2*half] = pack_h2(__float2half(S[jt][2]), __float2half(S[jt][3]));
            }
            #pragma unroll
            for (int dp = 0; dp < 4; dp++) {
                uint32_t r0,r1,r2,r3;
                LDSM4T(r0, r1, r2, r3,
                       smaddr(V + (kk*16 + laneRow)*KVP + dp*16 + laneKof));
                uint32_t vb0[2] = {r0, r1}, vb1[2] = {r2, r3};
                MMA_F16(Oacc[2*dp],   pa, vb0);
                MMA_F16(Oacc[2*dp+1], pa, vb1);
            }
        }
    }

    #pragma unroll
    for (int ch = 0; ch < 2; ch++) {
        const int q = q0 + wq*16 + (lane >> 2) + ch*8;
        if (q >= SEQ) continue;
        const float inv = 1.0f / l_run[ch];
        const long rowo = ((long)b*SEQ + q)*EMBED + h*64;
        #pragma unroll
        for (int jd = 0; jd < 8; jd++) {
            const int d = jd*8 + (lane & 3)*2;
            *reinterpret_cast<__half2*>(ao + rowo + d) =
                __half2(__float2half(Oacc[jd][ch*2 + 0]*inv),
                        __float2half(Oacc[jd][ch*2 + 1]*inv));
        }
    }
}

// ---------------- launch ----------------
extern "C" void kernel_launch(void* const* d_in, const int* in_sizes, int n_in,
                              void* d_out, int out_size)
{
    (void)in_sizes; (void)n_in; (void)out_size;
    const float* x      = (const float*)d_in[0];
    const float* mask   = (const float*)d_in[1];
    const float* qkv_w  = (const float*)d_in[2];
    const float* proj_w = (const float*)d_in[3];
    const float* proj_b = (const float*)d_in[4];
    const float* ln1_g  = (const float*)d_in[5];
    const float* ln1_b  = (const float*)d_in[6];
    const float* ln2_g  = (const float*)d_in[7];
    const float* ln2_b  = (const float*)d_in[8];
    const float* fc1_w  = (const float*)d_in[9];
    const float* fc1_b  = (const float*)d_in[10];
    const float* fc2_w  = (const float*)d_in[11];
    const float* fc2_b  = (const float*)d_in[12];
    float* out = (float*)d_out;

    h16 *xn, *q, *k, *v, *ao, *h1;
    h16 *wqkv, *wprj, *wfc1, *wfc2;
    float *xmid;
    cudaGetSymbolAddress((void**)&xn, g_xn);
    cudaGetSymbolAddress((void**)&q, g_q);
    cudaGetSymbolAddress((void**)&k, g_k);
    cudaGetSymbolAddress((void**)&v, g_v);
    cudaGetSymbolAddress((void**)&ao, g_ao);
    cudaGetSymbolAddress((void**)&h1, g_h1);
    cudaGetSymbolAddress((void**)&wqkv, g_wqkv);
    cudaGetSymbolAddress((void**)&wprj, g_wprj);
    cudaGetSymbolAddress((void**)&wfc1, g_wfc1);
    cudaGetSymbolAddress((void**)&wfc2, g_wfc2);
    cudaGetSymbolAddress((void**)&xmid, g_xmid);

    const int SMEM_G = smem_bytes(128, 128);   // 110592 B
    cudaFuncSetAttribute(tcgemm<128,128,2,4,1>, cudaFuncAttributeMaxDynamicSharedMemorySize, SMEM_G);
    cudaFuncSetAttribute(tcgemm<128,128,2,4,2>, cudaFuncAttributeMaxDynamicSharedMemorySize, SMEM_G);
    cudaFuncSetAttribute(tcgemm<128,128,2,4,3>, cudaFuncAttributeMaxDynamicSharedMemorySize, SMEM_G);
    cudaFuncSetAttribute(flash_kernel, cudaFuncAttributeMaxDynamicSharedMemorySize, FLASH_SMEM);

    const int MB = (MTOT + 127) / 128;   // 71

    wsplit_all<<<12288, dim3(32,8)>>>(qkv_w, wqkv, proj_w, wprj, fc1_w, wfc1, fc2_w, wfc2);

    ln_kernel<<<MTOT, 256>>>(x, ln1_g, ln1_b, xn);

    tcgemm<128,128,2,4,3><<<dim3(3072/128, MB, 1), 256, SMEM_G>>>(
        xn, wqkv, nullptr, nullptr,
        nullptr, q, k, v,
        MTOT, 3072, 1024, 1024, 1024, 0);

    flash_kernel<<<dim3(9, BATCH*NHEADS), 256, FLASH_SMEM>>>(
        q, k, v, mask, ao);

    tcgemm<128,128,2,4,1><<<dim3(EMBED/128, MB, 1), 256, SMEM_G>>>(
        ao, wprj, proj_b, x,
        xmid, nullptr, nullptr, nullptr,
        MTOT, EMBED, 1024, 1024, 1024, EMBED);

    ln_kernel<<<MTOT, 256>>>(xmid, ln2_g, ln2_b, xn);

    tcgemm<128,128,2,4,2><<<dim3(MLPH/128, MB, 1), 256, SMEM_G>>>(
        xn, wfc1, fc1_b, nullptr,
        nullptr, h1, nullptr, nullptr,
        MTOT, MLPH, 1024, 1024, 1024, MLPH);

    tcgemm<128,128,2,4,1><<<dim3(EMBED/128, MB, 1), 256, SMEM_G>>>(
        h1, wfc2, fc2_b, xmid,
        out, nullptr, nullptr, nullptr,
        MTOT, EMBED, 4096, 4096, 4096, EMBED);
}